// round 7
// baseline (speedup 1.0000x reference)
#include <cuda_runtime.h>
#include <cuda_fp16.h>
#include <cstdint>

// Problem constants
#define BATCH 4
#define SEQ   2048
#define DMODEL 2048
#define NHEAD 16
#define HDIM  128
#define MROWS (BATCH * SEQ)   // 8192

// ---------------------------------------------------------------------------
// Scratch (device globals; allocation in kernel_launch is forbidden)
// ---------------------------------------------------------------------------
__device__ __half g_Xq[(size_t)MROWS * DMODEL];
__device__ __half g_Xk[(size_t)MROWS * DMODEL];
__device__ __half g_Xv[(size_t)MROWS * DMODEL];
__device__ __half g_Wqh[(size_t)DMODEL * DMODEL];
__device__ __half g_Wql[(size_t)DMODEL * DMODEL];
__device__ __half g_Wkh[(size_t)DMODEL * DMODEL];
__device__ __half g_Wkl[(size_t)DMODEL * DMODEL];
__device__ __half g_Wvh[(size_t)DMODEL * DMODEL];
__device__ __half g_Wvl[(size_t)DMODEL * DMODEL];
__device__ __half g_Woh[(size_t)DMODEL * DMODEL];
__device__ __half g_Wol[(size_t)DMODEL * DMODEL];
__device__ __half g_Qh[(size_t)MROWS * DMODEL];
__device__ __half g_Kh[(size_t)MROWS * DMODEL];
__device__ __half g_Kl[(size_t)MROWS * DMODEL];
__device__ __half g_Vh[(size_t)MROWS * DMODEL];
__device__ __half g_Vl[(size_t)MROWS * DMODEL];
__device__ __half g_Ch[(size_t)MROWS * DMODEL];

// ---------------------------------------------------------------------------
// PTX helpers (sm_80-level: mma.sync / ldmatrix / cp.async)
// ---------------------------------------------------------------------------
__device__ __forceinline__ uint32_t smem_u32(const void* p) {
    uint32_t a;
    asm("{ .reg .u64 t; cvta.to.shared.u64 t, %1; cvt.u32.u64 %0, t; }"
        : "=r"(a) : "l"(p));
    return a;
}
__device__ __forceinline__ void ldsm4(uint32_t* r, uint32_t addr) {
    asm volatile("ldmatrix.sync.aligned.m8n8.x4.shared.b16 {%0,%1,%2,%3}, [%4];"
                 : "=r"(r[0]), "=r"(r[1]), "=r"(r[2]), "=r"(r[3]) : "r"(addr));
}
__device__ __forceinline__ void ldsm4t(uint32_t* r, uint32_t addr) {
    asm volatile("ldmatrix.sync.aligned.m8n8.x4.trans.shared.b16 {%0,%1,%2,%3}, [%4];"
                 : "=r"(r[0]), "=r"(r[1]), "=r"(r[2]), "=r"(r[3]) : "r"(addr));
}
__device__ __forceinline__ void mma_f16(float* d, const uint32_t* a,
                                        const uint32_t* b) {
    asm volatile(
        "mma.sync.aligned.m16n8k16.row.col.f32.f16.f16.f32 "
        "{%0,%1,%2,%3}, {%4,%5,%6,%7}, {%8,%9}, {%0,%1,%2,%3};"
        : "+f"(d[0]), "+f"(d[1]), "+f"(d[2]), "+f"(d[3])
        : "r"(a[0]), "r"(a[1]), "r"(a[2]), "r"(a[3]), "r"(b[0]), "r"(b[1]));
}
__device__ __forceinline__ void cp16(uint32_t dst, const void* src) {
    asm volatile("cp.async.cg.shared.global [%0], [%1], 16;"
                 :: "r"(dst), "l"(src) : "memory");
}
#define CP_COMMIT asm volatile("cp.async.commit_group;" ::: "memory")
#define CP_WAIT0  asm volatile("cp.async.wait_group 0;" ::: "memory")
#define CP_WAIT1  asm volatile("cp.async.wait_group 1;" ::: "memory")

// pack two fp32 -> half2 (first arg -> low half)
__device__ __forceinline__ uint32_t pack_h2(float lo, float hi) {
    uint32_t r;
    asm("cvt.rn.f16x2.f32 %0, %1, %2;" : "=r"(r) : "f"(hi), "f"(lo));
    return r;
}
__device__ __forceinline__ float2 h2_f2(uint32_t u) {
    __half2 h = *reinterpret_cast<__half2*>(&u);
    return __half22float2(h);
}

// ---------------------------------------------------------------------------
// Fused converts
// ---------------------------------------------------------------------------
#define NA4 (MROWS * DMODEL / 4)
#define NW4 (DMODEL * DMODEL / 4)

__global__ void __launch_bounds__(256) cvt3_f16(
    const float* __restrict__ x0, const float* __restrict__ x1,
    const float* __restrict__ x2, __half* __restrict__ h0,
    __half* __restrict__ h1, __half* __restrict__ h2)
{
    int i = blockIdx.x * 256 + threadIdx.x;
    int which = i / NA4;
    int j = i - which * NA4;
    const float* x = (which == 0) ? x0 : (which == 1) ? x1 : x2;
    __half* h = (which == 0) ? h0 : (which == 1) ? h1 : h2;
    float4 v = ((const float4*)x)[j];
    ((uint2*)h)[j] = make_uint2(pack_h2(v.x, v.y), pack_h2(v.z, v.w));
}

__global__ void __launch_bounds__(256) split4_f16(
    const float* __restrict__ w0, const float* __restrict__ w1,
    const float* __restrict__ w2, const float* __restrict__ w3,
    __half* __restrict__ h0, __half* __restrict__ l0,
    __half* __restrict__ h1, __half* __restrict__ l1,
    __half* __restrict__ h2, __half* __restrict__ l2,
    __half* __restrict__ h3, __half* __restrict__ l3)
{
    int i = blockIdx.x * 256 + threadIdx.x;
    int which = i / NW4;
    int j = i - which * NW4;
    const float* x = (which == 0) ? w0 : (which == 1) ? w1
                     : (which == 2) ? w2 : w3;
    __half* hi = (which == 0) ? h0 : (which == 1) ? h1
                 : (which == 2) ? h2 : h3;
    __half* lo = (which == 0) ? l0 : (which == 1) ? l1
                 : (which == 2) ? l2 : l3;
    float4 v = ((const float4*)x)[j];
    uint32_t a0 = pack_h2(v.x, v.y);
    uint32_t a1 = pack_h2(v.z, v.w);
    float2 f0 = h2_f2(a0), f1 = h2_f2(a1);
    ((uint2*)hi)[j] = make_uint2(a0, a1);
    ((uint2*)lo)[j] = make_uint2(pack_h2(v.x - f0.x, v.y - f0.y),
                                 pack_h2(v.z - f1.x, v.w - f1.y));
}

// ---------------------------------------------------------------------------
// fp16 2-term GEMM:  C = A @ W^T ≈ Ah·Wh + Ah·Wl
// CTA tile 256x128, BK=32, 8 warps in 4x2 grid, warp tile 64x64.
// 3-stage cp.async pipeline, 1 CTA/SM. Rows padded to 80 B.
// ---------------------------------------------------------------------------
#define G3_ROWB   80
#define G3_ATILE  (256 * G3_ROWB)              // 20480
#define G3_WTILE  (128 * G3_ROWB)              // 10240
#define G3_STAGE  (G3_ATILE + 2 * G3_WTILE)    // 40960
#define G3_SMEM   (3 * G3_STAGE)               // 122880

__device__ __forceinline__ void g3_load(
    uint32_t smb, int stage, const __half* __restrict__ A,
    const __half* __restrict__ Wh, const __half* __restrict__ Wl,
    int m0, int n0, int k0, int tid)
{
    const uint32_t base = smb + stage * G3_STAGE;
    const __half* Ap = A + (size_t)m0 * DMODEL + k0;
    #pragma unroll
    for (int i = 0; i < 4; i++) {
        int v = i * 256 + tid;          // 0..1023
        int r = v >> 2;                 // 0..255
        int c = (v & 3) * 16;
        cp16(base + r * G3_ROWB + c,
             (const char*)Ap + (size_t)r * DMODEL * 2 + c);
    }
    const __half* Ws[2] = {Wh + (size_t)n0 * DMODEL + k0,
                           Wl + (size_t)n0 * DMODEL + k0};
    #pragma unroll
    for (int t = 0; t < 2; t++) {
        #pragma unroll
        for (int i = 0; i < 2; i++) {
            int v = i * 256 + tid;      // 0..511
            int r = v >> 2;             // 0..127
            int c = (v & 3) * 16;
            cp16(base + G3_ATILE + t * G3_WTILE + r * G3_ROWB + c,
                 (const char*)Ws[t] + (size_t)r * DMODEL * 2 + c);
        }
    }
}

// Mainloop: warp (wm 0..3, wn 0..1), warp tile 64(m) x 64(n), acc[4][8][4]
__device__ __forceinline__ void g3_mainloop(
    uint32_t smb, const __half* __restrict__ A, const __half* __restrict__ Wh,
    const __half* __restrict__ Wl, int m0, int n0, int tid,
    float acc[4][8][4])
{
    const int lane = tid & 31;
    const int wid  = tid >> 5;
    const int wm = wid >> 1;           // 0..3
    const int wn = wid & 1;            // 0..1
    const int a_row = wm * 64 + (lane & 15);
    const int a_cb  = ((lane >> 4) & 1) * 16;
    const int b_row = wn * 64 + (lane & 7) + ((lane >> 4) << 3);
    const int b_cb  = ((lane >> 3) & 1) * 16;

    const int nchunks = DMODEL / 32;   // 64
    g3_load(smb, 0, A, Wh, Wl, m0, n0, 0, tid);
    CP_COMMIT;
    g3_load(smb, 1, A, Wh, Wl, m0, n0, 32, tid);
    CP_COMMIT;

    for (int c = 0; c < nchunks; c++) {
        CP_WAIT1;
        __syncthreads();
        if (c + 2 < nchunks)
            g3_load(smb, (c + 2) % 3, A, Wh, Wl, m0, n0, (c + 2) * 32, tid);
        CP_COMMIT;

        const uint32_t st = smb + (c % 3) * G3_STAGE;
        #pragma unroll
        for (int kk = 0; kk < 2; kk++) {
            const int kb = kk * 32;
            uint32_t bh[8][2], bl[8][2];
            #pragma unroll
            for (int nt2 = 0; nt2 < 4; nt2++) {
                uint32_t r4[4];
                uint32_t baddr = st + G3_ATILE +
                                 (b_row + nt2 * 16) * G3_ROWB + kb + b_cb;
                ldsm4(r4, baddr);
                bh[nt2 * 2][0] = r4[0]; bh[nt2 * 2][1] = r4[1];
                bh[nt2 * 2 + 1][0] = r4[2]; bh[nt2 * 2 + 1][1] = r4[3];
                ldsm4(r4, baddr + G3_WTILE);
                bl[nt2 * 2][0] = r4[0]; bl[nt2 * 2][1] = r4[1];
                bl[nt2 * 2 + 1][0] = r4[2]; bl[nt2 * 2 + 1][1] = r4[3];
            }
            #pragma unroll
            for (int mt = 0; mt < 4; mt++) {
                uint32_t ah[4];
                ldsm4(ah, st + (a_row + mt * 16) * G3_ROWB + kb + a_cb);
                #pragma unroll
                for (int nt = 0; nt < 8; nt++) {
                    mma_f16(acc[mt][nt], ah, bh[nt]);
                    mma_f16(acc[mt][nt], ah, bl[nt]);
                }
            }
        }
    }
}

// Fused Q/K/V projection GEMM: 1536 tiles (512 per matrix).
__global__ void __launch_bounds__(256, 1) gemm_qkv(
    const __half* __restrict__ xq, const __half* __restrict__ xk,
    const __half* __restrict__ xv,
    const __half* __restrict__ wqh, const __half* __restrict__ wql,
    const __half* __restrict__ wkh, const __half* __restrict__ wkl,
    const __half* __restrict__ wvh, const __half* __restrict__ wvl,
    __half* __restrict__ qh, __half* __restrict__ kh, __half* __restrict__ kl,
    __half* __restrict__ vh, __half* __restrict__ vl)
{
    extern __shared__ __align__(128) char sm[];
    const uint32_t smb = smem_u32(sm);
    const int t = blockIdx.x;
    const int which = t >> 9;           // 0..2  (512 tiles each)
    const int idx = t & 511;
    const int m0 = (idx >> 4) * 256;    // 32 m-tiles
    const int n0 = (idx & 15) * 128;    // 16 n-tiles
    const int tid = threadIdx.x;

    const __half* A  = (which == 0) ? xq  : (which == 1) ? xk  : xv;
    const __half* Wh = (which == 0) ? wqh : (which == 1) ? wkh : wvh;
    const __half* Wl = (which == 0) ? wql : (which == 1) ? wkl : wvl;
    __half* Oh = (which == 0) ? qh : (which == 1) ? kh : vh;
    __half* Ol = (which == 1) ? kl : vl;   // unused for which==0

    float acc[4][8][4];
    #pragma unroll
    for (int i = 0; i < 4; i++)
        #pragma unroll
        for (int j = 0; j < 8; j++)
            #pragma unroll
            for (int e = 0; e < 4; e++) acc[i][j][e] = 0.0f;

    g3_mainloop(smb, A, Wh, Wl, m0, n0, tid, acc);

    const int lane = tid & 31;
    const int wid  = tid >> 5;
    #pragma unroll
    for (int mt = 0; mt < 4; mt++) {
        const int row = m0 + (wid >> 1) * 64 + mt * 16 + (lane >> 2);
        #pragma unroll
        for (int nt = 0; nt < 8; nt++) {
            const int col = n0 + (wid & 1) * 64 + nt * 8 + (lane & 3) * 2;
            float a0 = acc[mt][nt][0], a1 = acc[mt][nt][1];
            float a2 = acc[mt][nt][2], a3 = acc[mt][nt][3];
            uint32_t h0 = pack_h2(a0, a1);
            uint32_t h1 = pack_h2(a2, a3);
            *(uint32_t*)&Oh[(size_t)row * DMODEL + col] = h0;
            *(uint32_t*)&Oh[(size_t)(row + 8) * DMODEL + col] = h1;
            if (which != 0) {
                float2 f0 = h2_f2(h0), f1 = h2_f2(h1);
                *(uint32_t*)&Ol[(size_t)row * DMODEL + col] =
                    pack_h2(a0 - f0.x, a1 - f0.y);
                *(uint32_t*)&Ol[(size_t)(row + 8) * DMODEL + col] =
                    pack_h2(a2 - f1.x, a3 - f1.y);
            }
        }
    }
}

// Output projection GEMM: fp32 result to d_out.
__global__ void __launch_bounds__(256, 1) gemm_out(
    const __half* __restrict__ A, const __half* __restrict__ Wh,
    const __half* __restrict__ Wl, float* __restrict__ C)
{
    extern __shared__ __align__(128) char sm[];
    const uint32_t smb = smem_u32(sm);
    const int m0 = blockIdx.y * 256;
    const int n0 = blockIdx.x * 128;
    const int tid = threadIdx.x;

    float acc[4][8][4];
    #pragma unroll
    for (int i = 0; i < 4; i++)
        #pragma unroll
        for (int j = 0; j < 8; j++)
            #pragma unroll
            for (int e = 0; e < 4; e++) acc[i][j][e] = 0.0f;

    g3_mainloop(smb, A, Wh, Wl, m0, n0, tid, acc);

    const int lane = tid & 31;
    const int wid  = tid >> 5;
    #pragma unroll
    for (int mt = 0; mt < 4; mt++) {
        const int row = m0 + (wid >> 1) * 64 + mt * 16 + (lane >> 2);
        #pragma unroll
        for (int nt = 0; nt < 8; nt++) {
            const int col = n0 + (wid & 1) * 64 + nt * 8 + (lane & 3) * 2;
            *(float2*)&C[(size_t)row * DMODEL + col] =
                make_float2(acc[mt][nt][0], acc[mt][nt][1]);
            *(float2*)&C[(size_t)(row + 8) * DMODEL + col] =
                make_float2(acc[mt][nt][2], acc[mt][nt][3]);
        }
    }
}

// ---------------------------------------------------------------------------
// Flash attention, fp16 HMMA, double-buffered KV, Q fragments in registers.
// (unchanged from R6)
// ---------------------------------------------------------------------------
#define FROWB 272
#define FQ    0
#define FSTG0 (128 * FROWB)
#define FSTG  (4 * 64 * FROWB)
#define FKH   0
#define FKL   (64 * FROWB)
#define FVH   (2 * 64 * FROWB)
#define FVL   (3 * 64 * FROWB)
#define FMSK  (FSTG0 + 2 * FSTG)
#define FSMEM (FMSK + 512)

__device__ __forceinline__ void fl_loadkv(
    uint32_t smb, int stg, const __half* __restrict__ kh,
    const __half* __restrict__ kl, const __half* __restrict__ vh,
    const __half* __restrict__ vl, const int* __restrict__ amask,
    int b, int h, int kt, int tid)
{
    const uint32_t base = smb + FSTG0 + stg * FSTG;
    const size_t krow0 = (size_t)b * SEQ + (size_t)kt * 64;
    #pragma unroll
    for (int i = 0; i < 4; i++) {
        int idx = i * 256 + tid;
        int r = idx >> 4;
        int c = (idx & 15) * 16;
        size_t go = ((krow0 + r) * DMODEL + h * HDIM) * 2 + c;
        cp16(base + FKH + r * FROWB + c, (const char*)kh + go);
        cp16(base + FKL + r * FROWB + c, (const char*)kl + go);
        cp16(base + FVH + r * FROWB + c, (const char*)vh + go);
        cp16(base + FVL + r * FROWB + c, (const char*)vl + go);
    }
    if (tid < 16)
        cp16(smb + FMSK + stg * 256 + tid * 16,
             (const char*)(amask + b * SEQ + kt * 64) + tid * 16);
}

__global__ void __launch_bounds__(256) flash_f16(
    const __half* __restrict__ qh, const __half* __restrict__ kh,
    const __half* __restrict__ kl, const __half* __restrict__ vh,
    const __half* __restrict__ vl, const int* __restrict__ amask,
    __half* __restrict__ chi)
{
    extern __shared__ __align__(128) char sm[];
    const uint32_t smb = smem_u32(sm);

    const int b  = blockIdx.z;
    const int h  = blockIdx.y;
    const int qt = (int)gridDim.x - 1 - (int)blockIdx.x;
    const int tid = threadIdx.x;
    const int wid = tid >> 5;
    const int lane = tid & 31;

    const size_t qrow0 = (size_t)b * SEQ + (size_t)qt * 128;

    #pragma unroll
    for (int i = 0; i < 8; i++) {
        int idx = i * 256 + tid;
        int r = idx >> 4;
        int c = (idx & 15) * 16;
        size_t go = ((qrow0 + r) * DMODEL + h * HDIM) * 2 + c;
        cp16(smb + FQ + r * FROWB + c, (const char*)qh + go);
    }
    fl_loadkv(smb, 0, kh, kl, vh, vl, amask, b, h, 0, tid);
    CP_COMMIT;

    float o[16][4];
    #pragma unroll
    for (int nt = 0; nt < 16; nt++)
        #pragma unroll
        for (int e = 0; e < 4; e++) o[nt][e] = 0.0f;
    float mA = -1e30f, mB = -1e30f, lA = 0.0f, lB = 0.0f;
    uint32_t qf[8][4];

    const float scale = 0.08838834764831843f;
    const int rA = lane >> 2;
    const int growA = qt * 128 + wid * 16 + rA;
    const int growB = growA + 8;
    const int ktmax = 2 * qt + 1;
    const uint32_t qbase = smb + FQ + (wid * 16 + (lane & 15)) * FROWB +
                           ((lane >> 4) & 1) * 16;
    const uint32_t kbase0 = ((lane & 7) + ((lane >> 4) << 3)) * FROWB +
                            ((lane >> 3) & 1) * 16;
    const uint32_t vbase0 = ((lane & 7) + ((lane >> 3) & 1) * 8) * FROWB +
                            (lane >> 4) * 16;

    for (int kt = 0; kt <= ktmax; kt++) {
        CP_WAIT0;
        __syncthreads();
        if (kt == 0) {
            #pragma unroll
            for (int kk = 0; kk < 8; kk++) ldsm4(qf[kk], qbase + kk * 32);
        }
        if (kt < ktmax)
            fl_loadkv(smb, (kt + 1) & 1, kh, kl, vh, vl, amask, b, h, kt + 1, tid);
        CP_COMMIT;

        const int stg = kt & 1;
        const uint32_t kvb = smb + FSTG0 + stg * FSTG;
        const int* Ms = (const int*)(sm + FMSK + stg * 256);

        float s[8][4];
        #pragma unroll
        for (int nt = 0; nt < 8; nt++)
            #pragma unroll
            for (int e = 0; e < 4; e++) s[nt][e] = 0.0f;

        #pragma unroll
        for (int kk = 0; kk < 8; kk++) {
            #pragma unroll
            for (int g = 0; g < 4; g++) {
                uint32_t kf[4], lf[4];
                uint32_t baddr = kvb + FKH + g * 16 * FROWB + kbase0 + kk * 32;
                ldsm4(kf, baddr);
                ldsm4(lf, baddr + FKL);
                mma_f16(s[2 * g], qf[kk], kf);
                mma_f16(s[2 * g], qf[kk], lf);
                mma_f16(s[2 * g + 1], qf[kk], kf + 2);
                mma_f16(s[2 * g + 1], qf[kk], lf + 2);
            }
        }

        float tmaxA = -1e30f, tmaxB = -1e30f;
        #pragma unroll
        for (int nt = 0; nt < 8; nt++) {
            int lc = nt * 8 + (lane & 3) * 2;
            int gc = kt * 64 + lc;
            int mk0 = Ms[lc], mk1 = Ms[lc + 1];
            float v0 = s[nt][0] * scale; if (gc > growA || !mk0) v0 = -10000.0f;
            float v1 = s[nt][1] * scale; if (gc + 1 > growA || !mk1) v1 = -10000.0f;
            float v2 = s[nt][2] * scale; if (gc > growB || !mk0) v2 = -10000.0f;
            float v3 = s[nt][3] * scale; if (gc + 1 > growB || !mk1) v3 = -10000.0f;
            s[nt][0] = v0; s[nt][1] = v1; s[nt][2] = v2; s[nt][3] = v3;
            tmaxA = fmaxf(tmaxA, fmaxf(v0, v1));
            tmaxB = fmaxf(tmaxB, fmaxf(v2, v3));
        }
        tmaxA = fmaxf(tmaxA, __shfl_xor_sync(0xffffffffu, tmaxA, 1));
        tmaxA = fmaxf(tmaxA, __shfl_xor_sync(0xffffffffu, tmaxA, 2));
        tmaxB = fmaxf(tmaxB, __shfl_xor_sync(0xffffffffu, tmaxB, 1));
        tmaxB = fmaxf(tmaxB, __shfl_xor_sync(0xffffffffu, tmaxB, 2));

        float mAn = fmaxf(mA, tmaxA), mBn = fmaxf(mB, tmaxB);
        float aAl = __expf(mA - mAn), aBl = __expf(mB - mBn);

        uint32_t phi[8][2];
        float sumA = 0.0f, sumB = 0.0f;
        #pragma unroll
        for (int nt = 0; nt < 8; nt++) {
            float p0 = __expf(s[nt][0] - mAn), p1 = __expf(s[nt][1] - mAn);
            float p2 = __expf(s[nt][2] - mBn), p3 = __expf(s[nt][3] - mBn);
            sumA += p0 + p1; sumB += p2 + p3;
            phi[nt][0] = pack_h2(p0, p1);
            phi[nt][1] = pack_h2(p2, p3);
        }
        sumA += __shfl_xor_sync(0xffffffffu, sumA, 1);
        sumA += __shfl_xor_sync(0xffffffffu, sumA, 2);
        sumB += __shfl_xor_sync(0xffffffffu, sumB, 1);
        sumB += __shfl_xor_sync(0xffffffffu, sumB, 2);
        lA = lA * aAl + sumA;
        lB = lB * aBl + sumB;
        mA = mAn; mB = mBn;

        #pragma unroll
        for (int nt = 0; nt < 16; nt++) {
            o[nt][0] *= aAl; o[nt][1] *= aAl;
            o[nt][2] *= aBl; o[nt][3] *= aBl;
        }

        #pragma unroll
        for (int t = 0; t < 4; t++) {
            uint32_t ah[4] = {phi[2 * t][0], phi[2 * t][1],
                              phi[2 * t + 1][0], phi[2 * t + 1][1]};
            #pragma unroll
            for (int g = 0; g < 8; g++) {
                uint32_t vf[4], wf[4];
                uint32_t vaddr = kvb + FVH + t * 16 * FROWB + vbase0 + g * 32;
                ldsm4t(vf, vaddr);
                ldsm4t(wf, vaddr + (FVL - FVH));
                mma_f16(o[2 * g], ah, vf);
                mma_f16(o[2 * g], ah, wf);
                mma_f16(o[2 * g + 1], ah, vf + 2);
                mma_f16(o[2 * g + 1], ah, wf + 2);
            }
        }
    }

    const float invA = 1.0f / lA, invB = 1.0f / lB;
    const size_t rgA = qrow0 + wid * 16 + rA;
    const size_t rgB = rgA + 8;
    #pragma unroll
    for (int nt = 0; nt < 16; nt++) {
        int col = h * HDIM + nt * 8 + (lane & 3) * 2;
        *(uint32_t*)&chi[rgA * DMODEL + col] =
            pack_h2(o[nt][0] * invA, o[nt][1] * invA);
        *(uint32_t*)&chi[rgB * DMODEL + col] =
            pack_h2(o[nt][2] * invB, o[nt][3] * invB);
    }
}

// ---------------------------------------------------------------------------
// Launch
// ---------------------------------------------------------------------------
extern "C" void kernel_launch(void* const* d_in, const int* in_sizes, int n_in,
                              void* d_out, int out_size)
{
    const float* query = (const float*)d_in[0];
    const float* key   = (const float*)d_in[1];
    const float* value = (const float*)d_in[2];
    const int*   amask = (const int*)  d_in[3];
    const float* Wq    = (const float*)d_in[4];
    const float* Wk    = (const float*)d_in[5];
    const float* Wv    = (const float*)d_in[6];
    const float* Wo    = (const float*)d_in[7];
    float* out = (float*)d_out;

    __half *xq, *xk, *xv, *wqh, *wql, *wkh, *wkl, *wvh, *wvl, *woh, *wol;
    __half *qh, *khb, *klb, *vhb, *vlb, *chb;
    cudaGetSymbolAddress((void**)&xq,  g_Xq);
    cudaGetSymbolAddress((void**)&xk,  g_Xk);
    cudaGetSymbolAddress((void**)&xv,  g_Xv);
    cudaGetSymbolAddress((void**)&wqh, g_Wqh);
    cudaGetSymbolAddress((void**)&wql, g_Wql);
    cudaGetSymbolAddress((void**)&wkh, g_Wkh);
    cudaGetSymbolAddress((void**)&wkl, g_Wkl);
    cudaGetSymbolAddress((void**)&wvh, g_Wvh);
    cudaGetSymbolAddress((void**)&wvl, g_Wvl);
    cudaGetSymbolAddress((void**)&woh, g_Woh);
    cudaGetSymbolAddress((void**)&wol, g_Wol);
    cudaGetSymbolAddress((void**)&qh,  g_Qh);
    cudaGetSymbolAddress((void**)&khb, g_Kh);
    cudaGetSymbolAddress((void**)&klb, g_Kl);
    cudaGetSymbolAddress((void**)&vhb, g_Vh);
    cudaGetSymbolAddress((void**)&vlb, g_Vl);
    cudaGetSymbolAddress((void**)&chb, g_Ch);

    cudaFuncSetAttribute(gemm_qkv,
                         cudaFuncAttributeMaxDynamicSharedMemorySize, G3_SMEM);
    cudaFuncSetAttribute(gemm_out,
                         cudaFuncAttributeMaxDynamicSharedMemorySize, G3_SMEM);
    cudaFuncSetAttribute(flash_f16,
                         cudaFuncAttributeMaxDynamicSharedMemorySize, FSMEM);

    split4_f16<<<4 * NW4 / 256, 256>>>(Wq, Wk, Wv, Wo,
                                       wqh, wql, wkh, wkl, wvh, wvl, woh, wol);
    cvt3_f16<<<3 * NA4 / 256, 256>>>(query, key, value, xq, xk, xv);

    gemm_qkv<<<1536, 256, G3_SMEM>>>(xq, xk, xv, wqh, wql, wkh, wkl, wvh, wvl,
                                     qh, khb, klb, vhb, vlb);

    flash_f16<<<dim3(SEQ / 128, NHEAD, BATCH), 256, FSMEM>>>(
        qh, khb, klb, vhb, vlb, amask, chb);

    gemm_out<<<dim3(DMODEL / 128, MROWS / 256), 256, G3_SMEM>>>(chb, woh, wol, out);
}

// round 8
// speedup vs baseline: 1.0720x; 1.0720x over previous
#include <cuda_runtime.h>
#include <cuda_fp16.h>
#include <cstdint>

// Problem constants
#define BATCH 4
#define SEQ   2048
#define DMODEL 2048
#define NHEAD 16
#define HDIM  128
#define MROWS (BATCH * SEQ)   // 8192

// ---------------------------------------------------------------------------
// Scratch (device globals; allocation in kernel_launch is forbidden)
// ---------------------------------------------------------------------------
__device__ __half g_Xq[(size_t)MROWS * DMODEL];
__device__ __half g_Xk[(size_t)MROWS * DMODEL];
__device__ __half g_Xv[(size_t)MROWS * DMODEL];
__device__ __half g_Wqh[(size_t)DMODEL * DMODEL];
__device__ __half g_Wql[(size_t)DMODEL * DMODEL];
__device__ __half g_Wkh[(size_t)DMODEL * DMODEL];
__device__ __half g_Wkl[(size_t)DMODEL * DMODEL];
__device__ __half g_Wvh[(size_t)DMODEL * DMODEL];
__device__ __half g_Wvl[(size_t)DMODEL * DMODEL];
__device__ __half g_Woh[(size_t)DMODEL * DMODEL];
__device__ __half g_Wol[(size_t)DMODEL * DMODEL];
__device__ __half g_Qh[(size_t)MROWS * DMODEL];
__device__ __half g_Kh[(size_t)MROWS * DMODEL];
__device__ __half g_Kl[(size_t)MROWS * DMODEL];
__device__ __half g_Vh[(size_t)MROWS * DMODEL];
__device__ __half g_Vl[(size_t)MROWS * DMODEL];
__device__ __half g_Ch[(size_t)MROWS * DMODEL];

// ---------------------------------------------------------------------------
// PTX helpers (sm_80-level: mma.sync / ldmatrix / cp.async)
// ---------------------------------------------------------------------------
__device__ __forceinline__ uint32_t smem_u32(const void* p) {
    uint32_t a;
    asm("{ .reg .u64 t; cvta.to.shared.u64 t, %1; cvt.u32.u64 %0, t; }"
        : "=r"(a) : "l"(p));
    return a;
}
__device__ __forceinline__ void ldsm4(uint32_t* r, uint32_t addr) {
    asm volatile("ldmatrix.sync.aligned.m8n8.x4.shared.b16 {%0,%1,%2,%3}, [%4];"
                 : "=r"(r[0]), "=r"(r[1]), "=r"(r[2]), "=r"(r[3]) : "r"(addr));
}
__device__ __forceinline__ void ldsm4t(uint32_t* r, uint32_t addr) {
    asm volatile("ldmatrix.sync.aligned.m8n8.x4.trans.shared.b16 {%0,%1,%2,%3}, [%4];"
                 : "=r"(r[0]), "=r"(r[1]), "=r"(r[2]), "=r"(r[3]) : "r"(addr));
}
__device__ __forceinline__ void mma_f16(float* d, const uint32_t* a,
                                        const uint32_t* b) {
    asm volatile(
        "mma.sync.aligned.m16n8k16.row.col.f32.f16.f16.f32 "
        "{%0,%1,%2,%3}, {%4,%5,%6,%7}, {%8,%9}, {%0,%1,%2,%3};"
        : "+f"(d[0]), "+f"(d[1]), "+f"(d[2]), "+f"(d[3])
        : "r"(a[0]), "r"(a[1]), "r"(a[2]), "r"(a[3]), "r"(b[0]), "r"(b[1]));
}
__device__ __forceinline__ void cp16(uint32_t dst, const void* src) {
    asm volatile("cp.async.cg.shared.global [%0], [%1], 16;"
                 :: "r"(dst), "l"(src) : "memory");
}
#define CP_COMMIT asm volatile("cp.async.commit_group;" ::: "memory")
#define CP_WAIT0  asm volatile("cp.async.wait_group 0;" ::: "memory")
#define CP_WAIT1  asm volatile("cp.async.wait_group 1;" ::: "memory")

// pack two fp32 -> half2 (first arg -> low half)
__device__ __forceinline__ uint32_t pack_h2(float lo, float hi) {
    uint32_t r;
    asm("cvt.rn.f16x2.f32 %0, %1, %2;" : "=r"(r) : "f"(hi), "f"(lo));
    return r;
}
__device__ __forceinline__ float2 h2_f2(uint32_t u) {
    __half2 h = *reinterpret_cast<__half2*>(&u);
    return __half22float2(h);
}

#define QSCALE 0.08838834764831843f   // 1/sqrt(128), folded into Q

// ---------------------------------------------------------------------------
// Fused converts
// ---------------------------------------------------------------------------
#define NA4 (MROWS * DMODEL / 4)
#define NW4 (DMODEL * DMODEL / 4)

__global__ void __launch_bounds__(256) cvt3_f16(
    const float* __restrict__ x0, const float* __restrict__ x1,
    const float* __restrict__ x2, __half* __restrict__ h0,
    __half* __restrict__ h1, __half* __restrict__ h2)
{
    int i = blockIdx.x * 256 + threadIdx.x;
    int which = i / NA4;
    int j = i - which * NA4;
    const float* x = (which == 0) ? x0 : (which == 1) ? x1 : x2;
    __half* h = (which == 0) ? h0 : (which == 1) ? h1 : h2;
    float4 v = ((const float4*)x)[j];
    ((uint2*)h)[j] = make_uint2(pack_h2(v.x, v.y), pack_h2(v.z, v.w));
}

__global__ void __launch_bounds__(256) split4_f16(
    const float* __restrict__ w0, const float* __restrict__ w1,
    const float* __restrict__ w2, const float* __restrict__ w3,
    __half* __restrict__ h0, __half* __restrict__ l0,
    __half* __restrict__ h1, __half* __restrict__ l1,
    __half* __restrict__ h2, __half* __restrict__ l2,
    __half* __restrict__ h3, __half* __restrict__ l3)
{
    int i = blockIdx.x * 256 + threadIdx.x;
    int which = i / NW4;
    int j = i - which * NW4;
    const float* x = (which == 0) ? w0 : (which == 1) ? w1
                     : (which == 2) ? w2 : w3;
    __half* hi = (which == 0) ? h0 : (which == 1) ? h1
                 : (which == 2) ? h2 : h3;
    __half* lo = (which == 0) ? l0 : (which == 1) ? l1
                 : (which == 2) ? l2 : l3;
    float4 v = ((const float4*)x)[j];
    uint32_t a0 = pack_h2(v.x, v.y);
    uint32_t a1 = pack_h2(v.z, v.w);
    float2 f0 = h2_f2(a0), f1 = h2_f2(a1);
    ((uint2*)hi)[j] = make_uint2(a0, a1);
    ((uint2*)lo)[j] = make_uint2(pack_h2(v.x - f0.x, v.y - f0.y),
                                 pack_h2(v.z - f1.x, v.w - f1.y));
}

// ---------------------------------------------------------------------------
// fp16 2-term GEMM (R6 config, reverted):  C = A @ W^T ≈ Ah·Wh + Ah·Wl
// CTA 128x128, BK=32, 8 warps (2x4, warp 64x32), 3-stage pipeline, 2 CTAs/SM.
// ---------------------------------------------------------------------------
#define G2_ROWB  80
#define G2_TILE  (128 * G2_ROWB)     // 10240
#define G2_STAGE (3 * G2_TILE)       // 30720 (A, Wh, Wl)
#define G2_SMEM  (3 * G2_STAGE)      // 92160

__device__ __forceinline__ void g2_load(
    uint32_t smb, int stage, const __half* __restrict__ A,
    const __half* __restrict__ Wh, const __half* __restrict__ Wl,
    int m0, int n0, int k0, int tid)
{
    const __half* srcs[3] = {A + (size_t)m0 * DMODEL + k0,
                             Wh + (size_t)n0 * DMODEL + k0,
                             Wl + (size_t)n0 * DMODEL + k0};
    #pragma unroll
    for (int t = 0; t < 3; t++) {
        #pragma unroll
        for (int i = 0; i < 2; i++) {
            int v = i * 256 + tid;
            int r = v >> 2;
            int c = (v & 3) * 16;
            cp16(smb + stage * G2_STAGE + t * G2_TILE + r * G2_ROWB + c,
                 (const char*)srcs[t] + (size_t)r * DMODEL * 2 + c);
        }
    }
}

__device__ __forceinline__ void g2_mainloop(
    uint32_t smb, const __half* __restrict__ A, const __half* __restrict__ Wh,
    const __half* __restrict__ Wl, int m0, int n0, int tid,
    float acc[4][4][4])
{
    const int lane = tid & 31;
    const int wid  = tid >> 5;
    const int wm = wid >> 2;
    const int wn = wid & 3;
    const int a_row = wm * 64 + (lane & 15);
    const int a_cb  = ((lane >> 4) & 1) * 16;
    const int b_row = wn * 32 + (lane & 7) + ((lane >> 4) << 3);
    const int b_cb  = ((lane >> 3) & 1) * 16;

    const int nchunks = DMODEL / 32;   // 64
    g2_load(smb, 0, A, Wh, Wl, m0, n0, 0, tid);
    CP_COMMIT;
    g2_load(smb, 1, A, Wh, Wl, m0, n0, 32, tid);
    CP_COMMIT;

    for (int c = 0; c < nchunks; c++) {
        CP_WAIT1;
        __syncthreads();
        if (c + 2 < nchunks)
            g2_load(smb, (c + 2) % 3, A, Wh, Wl, m0, n0, (c + 2) * 32, tid);
        CP_COMMIT;

        const uint32_t st = smb + (c % 3) * G2_STAGE;
        #pragma unroll
        for (int kk = 0; kk < 2; kk++) {
            const int kb = kk * 32;
            uint32_t bh[4][2], bl[4][2];
            #pragma unroll
            for (int nt2 = 0; nt2 < 2; nt2++) {
                uint32_t r4[4];
                uint32_t baddr = st + G2_TILE +
                                 (b_row + nt2 * 16) * G2_ROWB + kb + b_cb;
                ldsm4(r4, baddr);
                bh[nt2 * 2][0] = r4[0]; bh[nt2 * 2][1] = r4[1];
                bh[nt2 * 2 + 1][0] = r4[2]; bh[nt2 * 2 + 1][1] = r4[3];
                ldsm4(r4, baddr + G2_TILE);
                bl[nt2 * 2][0] = r4[0]; bl[nt2 * 2][1] = r4[1];
                bl[nt2 * 2 + 1][0] = r4[2]; bl[nt2 * 2 + 1][1] = r4[3];
            }
            #pragma unroll
            for (int mt = 0; mt < 4; mt++) {
                uint32_t ah[4];
                ldsm4(ah, st + (a_row + mt * 16) * G2_ROWB + kb + a_cb);
                #pragma unroll
                for (int nt = 0; nt < 4; nt++) {
                    mma_f16(acc[mt][nt], ah, bh[nt]);
                    mma_f16(acc[mt][nt], ah, bl[nt]);
                }
            }
        }
    }
}

// Fused Q/K/V projection GEMM: 3072 tiles. Q gets 1/sqrt(HDIM) folded in.
__global__ void __launch_bounds__(256, 2) gemm_qkv(
    const __half* __restrict__ xq, const __half* __restrict__ xk,
    const __half* __restrict__ xv,
    const __half* __restrict__ wqh, const __half* __restrict__ wql,
    const __half* __restrict__ wkh, const __half* __restrict__ wkl,
    const __half* __restrict__ wvh, const __half* __restrict__ wvl,
    __half* __restrict__ qh, __half* __restrict__ kh, __half* __restrict__ kl,
    __half* __restrict__ vh, __half* __restrict__ vl)
{
    extern __shared__ __align__(128) char sm[];
    const uint32_t smb = smem_u32(sm);
    const int t = blockIdx.x;
    const int which = t >> 10;
    const int idx = t & 1023;
    const int m0 = (idx >> 4) * 128;
    const int n0 = (idx & 15) * 128;
    const int tid = threadIdx.x;

    const __half* A  = (which == 0) ? xq  : (which == 1) ? xk  : xv;
    const __half* Wh = (which == 0) ? wqh : (which == 1) ? wkh : wvh;
    const __half* Wl = (which == 0) ? wql : (which == 1) ? wkl : wvl;
    __half* Oh = (which == 0) ? qh : (which == 1) ? kh : vh;
    __half* Ol = (which == 1) ? kl : vl;

    float acc[4][4][4];
    #pragma unroll
    for (int i = 0; i < 4; i++)
        #pragma unroll
        for (int j = 0; j < 4; j++)
            #pragma unroll
            for (int e = 0; e < 4; e++) acc[i][j][e] = 0.0f;

    g2_mainloop(smb, A, Wh, Wl, m0, n0, tid, acc);

    const int lane = tid & 31;
    const int wid  = tid >> 5;
    const float sc = (which == 0) ? QSCALE : 1.0f;
    #pragma unroll
    for (int mt = 0; mt < 4; mt++) {
        const int row = m0 + (wid >> 2) * 64 + mt * 16 + (lane >> 2);
        #pragma unroll
        for (int nt = 0; nt < 4; nt++) {
            const int col = n0 + (wid & 3) * 32 + nt * 8 + (lane & 3) * 2;
            float a0 = acc[mt][nt][0] * sc, a1 = acc[mt][nt][1] * sc;
            float a2 = acc[mt][nt][2] * sc, a3 = acc[mt][nt][3] * sc;
            uint32_t h0 = pack_h2(a0, a1);
            uint32_t h1 = pack_h2(a2, a3);
            *(uint32_t*)&Oh[(size_t)row * DMODEL + col] = h0;
            *(uint32_t*)&Oh[(size_t)(row + 8) * DMODEL + col] = h1;
            if (which != 0) {
                float2 f0 = h2_f2(h0), f1 = h2_f2(h1);
                *(uint32_t*)&Ol[(size_t)row * DMODEL + col] =
                    pack_h2(a0 - f0.x, a1 - f0.y);
                *(uint32_t*)&Ol[(size_t)(row + 8) * DMODEL + col] =
                    pack_h2(a2 - f1.x, a3 - f1.y);
            }
        }
    }
}

// Output projection GEMM: fp32 result to d_out.
__global__ void __launch_bounds__(256, 2) gemm_out(
    const __half* __restrict__ A, const __half* __restrict__ Wh,
    const __half* __restrict__ Wl, float* __restrict__ C)
{
    extern __shared__ __align__(128) char sm[];
    const uint32_t smb = smem_u32(sm);
    const int m0 = blockIdx.y * 128;
    const int n0 = blockIdx.x * 128;
    const int tid = threadIdx.x;

    float acc[4][4][4];
    #pragma unroll
    for (int i = 0; i < 4; i++)
        #pragma unroll
        for (int j = 0; j < 4; j++)
            #pragma unroll
            for (int e = 0; e < 4; e++) acc[i][j][e] = 0.0f;

    g2_mainloop(smb, A, Wh, Wl, m0, n0, tid, acc);

    const int lane = tid & 31;
    const int wid  = tid >> 5;
    #pragma unroll
    for (int mt = 0; mt < 4; mt++) {
        const int row = m0 + (wid >> 2) * 64 + mt * 16 + (lane >> 2);
        #pragma unroll
        for (int nt = 0; nt < 4; nt++) {
            const int col = n0 + (wid & 3) * 32 + nt * 8 + (lane & 3) * 2;
            *(float2*)&C[(size_t)row * DMODEL + col] =
                make_float2(acc[mt][nt][0], acc[mt][nt][1]);
            *(float2*)&C[(size_t)(row + 8) * DMODEL + col] =
                make_float2(acc[mt][nt][2], acc[mt][nt][3]);
        }
    }
}

// ---------------------------------------------------------------------------
// Flash attention, fp16 HMMA. BQ=64, BKV=64, 4 warps/CTA, 2 CTAs/SM.
// Single KV buffer per CTA; cross-CTA overlap hides load latency.
// Q pre-scaled by 1/sqrt(HDIM). Warp-uniform fast paths for masking and
// O-rescale.
// ---------------------------------------------------------------------------
#define FB_ROWB 272
#define FB_KH   0
#define FB_KL   (64 * FB_ROWB)
#define FB_VH   (2 * 64 * FB_ROWB)
#define FB_VL   (3 * 64 * FB_ROWB)
#define FB_Q    (4 * 64 * FB_ROWB)          // 69632
#define FB_MSK  (FB_Q + 64 * FB_ROWB)       // 87040
#define FB_SMEM (FB_MSK + 256)              // 87296 -> 2 CTAs/SM

__device__ __forceinline__ void fl_loadkv64(
    uint32_t smb, const __half* __restrict__ kh,
    const __half* __restrict__ kl, const __half* __restrict__ vh,
    const __half* __restrict__ vl, const int* __restrict__ amask,
    int b, int h, int kt, int tid)
{
    const size_t krow0 = (size_t)b * SEQ + (size_t)kt * 64;
    #pragma unroll
    for (int i = 0; i < 8; i++) {
        int idx = i * 128 + tid;
        int r = idx >> 4;
        int c = (idx & 15) * 16;
        size_t go = ((krow0 + r) * DMODEL + h * HDIM) * 2 + c;
        cp16(smb + FB_KH + r * FB_ROWB + c, (const char*)kh + go);
        cp16(smb + FB_KL + r * FB_ROWB + c, (const char*)kl + go);
        cp16(smb + FB_VH + r * FB_ROWB + c, (const char*)vh + go);
        cp16(smb + FB_VL + r * FB_ROWB + c, (const char*)vl + go);
    }
    if (tid < 16)
        cp16(smb + FB_MSK + tid * 16,
             (const char*)(amask + b * SEQ + kt * 64) + tid * 16);
}

__global__ void __launch_bounds__(128) flash_f16(
    const __half* __restrict__ qh, const __half* __restrict__ kh,
    const __half* __restrict__ kl, const __half* __restrict__ vh,
    const __half* __restrict__ vl, const int* __restrict__ amask,
    __half* __restrict__ chi)
{
    extern __shared__ __align__(128) char sm[];
    const uint32_t smb = smem_u32(sm);

    const int b  = blockIdx.z;
    const int h  = blockIdx.y;
    const int qt = (int)gridDim.x - 1 - (int)blockIdx.x;   // heavy tiles first
    const int tid = threadIdx.x;
    const int wid = tid >> 5;       // 0..3
    const int lane = tid & 31;

    const size_t qrow0 = (size_t)b * SEQ + (size_t)qt * 64;

    // Q tile (pre-scaled) -> smem
    #pragma unroll
    for (int i = 0; i < 8; i++) {
        int idx = i * 128 + tid;
        int r = idx >> 4;
        int c = (idx & 15) * 16;
        size_t go = ((qrow0 + r) * DMODEL + h * HDIM) * 2 + c;
        cp16(smb + FB_Q + r * FB_ROWB + c, (const char*)qh + go);
    }
    fl_loadkv64(smb, kh, kl, vh, vl, amask, b, h, 0, tid);
    CP_COMMIT;

    float o[16][4];
    #pragma unroll
    for (int nt = 0; nt < 16; nt++)
        #pragma unroll
        for (int e = 0; e < 4; e++) o[nt][e] = 0.0f;
    float mA = -1e30f, mB = -1e30f, lA = 0.0f, lB = 0.0f;
    uint32_t qf[8][4];

    const int rA = lane >> 2;
    const int growA = qt * 64 + wid * 16 + rA;
    const int growB = growA + 8;
    const uint32_t qbase = smb + FB_Q + (wid * 16 + (lane & 15)) * FB_ROWB +
                           ((lane >> 4) & 1) * 16;
    const uint32_t kbase0 = smb + FB_KH +
                            ((lane & 7) + ((lane >> 4) << 3)) * FB_ROWB +
                            ((lane >> 3) & 1) * 16;
    const uint32_t vbase0 = smb + FB_VH +
                            ((lane & 7) + ((lane >> 3) & 1) * 8) * FB_ROWB +
                            (lane >> 4) * 16;

    for (int kt = 0; kt <= qt; kt++) {
        CP_WAIT0;
        __syncthreads();
        if (kt == 0) {
            #pragma unroll
            for (int kk = 0; kk < 8; kk++) ldsm4(qf[kk], qbase + kk * 32);
        }

        // ---- S = Qs (Kh+Kl)^T  (scale already folded into Q) ----
        float s[8][4];
        #pragma unroll
        for (int nt = 0; nt < 8; nt++)
            #pragma unroll
            for (int e = 0; e < 4; e++) s[nt][e] = 0.0f;

        #pragma unroll
        for (int kk = 0; kk < 8; kk++) {
            #pragma unroll
            for (int g = 0; g < 4; g++) {
                uint32_t kf[4], lf[4];
                uint32_t baddr = kbase0 + g * 16 * FB_ROWB + kk * 32;
                ldsm4(kf, baddr);
                ldsm4(lf, baddr + FB_KL);
                mma_f16(s[2 * g], qf[kk], kf);
                mma_f16(s[2 * g], qf[kk], lf);
                mma_f16(s[2 * g + 1], qf[kk], kf + 2);
                mma_f16(s[2 * g + 1], qf[kk], lf + 2);
            }
        }

        // ---- mask (warp-uniform fast path) + row max ----
        const int* Ms = (const int*)(sm + FB_MSK);
        int mybit = (Ms[lane] != 0) & (Ms[lane + 32] != 0);
        bool allones = (__ballot_sync(0xffffffffu, mybit) == 0xffffffffu);
        float tmaxA = -1e30f, tmaxB = -1e30f;
        if (allones && (kt * 64 + 63 <= qt * 64 + wid * 16)) {
            #pragma unroll
            for (int nt = 0; nt < 8; nt++) {
                tmaxA = fmaxf(tmaxA, fmaxf(s[nt][0], s[nt][1]));
                tmaxB = fmaxf(tmaxB, fmaxf(s[nt][2], s[nt][3]));
            }
        } else {
            #pragma unroll
            for (int nt = 0; nt < 8; nt++) {
                int lc = nt * 8 + (lane & 3) * 2;
                int gc = kt * 64 + lc;
                int mk0 = Ms[lc], mk1 = Ms[lc + 1];
                float v0 = s[nt][0]; if (gc > growA || !mk0) v0 = -10000.0f;
                float v1 = s[nt][1]; if (gc + 1 > growA || !mk1) v1 = -10000.0f;
                float v2 = s[nt][2]; if (gc > growB || !mk0) v2 = -10000.0f;
                float v3 = s[nt][3]; if (gc + 1 > growB || !mk1) v3 = -10000.0f;
                s[nt][0] = v0; s[nt][1] = v1; s[nt][2] = v2; s[nt][3] = v3;
                tmaxA = fmaxf(tmaxA, fmaxf(v0, v1));
                tmaxB = fmaxf(tmaxB, fmaxf(v2, v3));
            }
        }
        tmaxA = fmaxf(tmaxA, __shfl_xor_sync(0xffffffffu, tmaxA, 1));
        tmaxA = fmaxf(tmaxA, __shfl_xor_sync(0xffffffffu, tmaxA, 2));
        tmaxB = fmaxf(tmaxB, __shfl_xor_sync(0xffffffffu, tmaxB, 1));
        tmaxB = fmaxf(tmaxB, __shfl_xor_sync(0xffffffffu, tmaxB, 2));

        float mAn = fmaxf(mA, tmaxA), mBn = fmaxf(mB, tmaxB);
        float aAl = __expf(mA - mAn), aBl = __expf(mB - mBn);

        // ---- P = exp(S - m) -> fp16 fragments ----
        uint32_t phi[8][2];
        float sumA = 0.0f, sumB = 0.0f;
        #pragma unroll
        for (int nt = 0; nt < 8; nt++) {
            float p0 = __expf(s[nt][0] - mAn), p1 = __expf(s[nt][1] - mAn);
            float p2 = __expf(s[nt][2] - mBn), p3 = __expf(s[nt][3] - mBn);
            sumA += p0 + p1; sumB += p2 + p3;
            phi[nt][0] = pack_h2(p0, p1);
            phi[nt][1] = pack_h2(p2, p3);
        }
        sumA += __shfl_xor_sync(0xffffffffu, sumA, 1);
        sumA += __shfl_xor_sync(0xffffffffu, sumA, 2);
        sumB += __shfl_xor_sync(0xffffffffu, sumB, 1);
        sumB += __shfl_xor_sync(0xffffffffu, sumB, 2);
        lA = lA * aAl + sumA;
        lB = lB * aBl + sumB;
        mA = mAn; mB = mBn;

        // ---- O rescale (skip when no row max moved in this warp) ----
        if (__ballot_sync(0xffffffffu,
                          (aAl == 1.0f) && (aBl == 1.0f)) != 0xffffffffu) {
            #pragma unroll
            for (int nt = 0; nt < 16; nt++) {
                o[nt][0] *= aAl; o[nt][1] *= aAl;
                o[nt][2] *= aBl; o[nt][3] *= aBl;
            }
        }

        // ---- O += P (Vh+Vl) ----
        #pragma unroll
        for (int t = 0; t < 4; t++) {
            uint32_t ah[4] = {phi[2 * t][0], phi[2 * t][1],
                              phi[2 * t + 1][0], phi[2 * t + 1][1]};
            #pragma unroll
            for (int g = 0; g < 8; g++) {
                uint32_t vf[4], wf[4];
                uint32_t vaddr = vbase0 + t * 16 * FB_ROWB + g * 32;
                ldsm4t(vf, vaddr);
                ldsm4t(wf, vaddr + (FB_VL - FB_VH));
                mma_f16(o[2 * g], ah, vf);
                mma_f16(o[2 * g], ah, wf);
                mma_f16(o[2 * g + 1], ah, vf + 2);
                mma_f16(o[2 * g + 1], ah, wf + 2);
            }
        }

        __syncthreads();   // all warps done reading the KV buffer
        if (kt < qt)
            fl_loadkv64(smb, kh, kl, vh, vl, amask, b, h, kt + 1, tid);
        CP_COMMIT;
    }

    // ---- normalize + store context (fp16 hi only) ----
    const float invA = 1.0f / lA, invB = 1.0f / lB;
    const size_t rgA = qrow0 + wid * 16 + rA;
    const size_t rgB = rgA + 8;
    #pragma unroll
    for (int nt = 0; nt < 16; nt++) {
        int col = h * HDIM + nt * 8 + (lane & 3) * 2;
        *(uint32_t*)&chi[rgA * DMODEL + col] =
            pack_h2(o[nt][0] * invA, o[nt][1] * invA);
        *(uint32_t*)&chi[rgB * DMODEL + col] =
            pack_h2(o[nt][2] * invB, o[nt][3] * invB);
    }
}

// ---------------------------------------------------------------------------
// Launch
// ---------------------------------------------------------------------------
extern "C" void kernel_launch(void* const* d_in, const int* in_sizes, int n_in,
                              void* d_out, int out_size)
{
    const float* query = (const float*)d_in[0];
    const float* key   = (const float*)d_in[1];
    const float* value = (const float*)d_in[2];
    const int*   amask = (const int*)  d_in[3];
    const float* Wq    = (const float*)d_in[4];
    const float* Wk    = (const float*)d_in[5];
    const float* Wv    = (const float*)d_in[6];
    const float* Wo    = (const float*)d_in[7];
    float* out = (float*)d_out;

    __half *xq, *xk, *xv, *wqh, *wql, *wkh, *wkl, *wvh, *wvl, *woh, *wol;
    __half *qh, *khb, *klb, *vhb, *vlb, *chb;
    cudaGetSymbolAddress((void**)&xq,  g_Xq);
    cudaGetSymbolAddress((void**)&xk,  g_Xk);
    cudaGetSymbolAddress((void**)&xv,  g_Xv);
    cudaGetSymbolAddress((void**)&wqh, g_Wqh);
    cudaGetSymbolAddress((void**)&wql, g_Wql);
    cudaGetSymbolAddress((void**)&wkh, g_Wkh);
    cudaGetSymbolAddress((void**)&wkl, g_Wkl);
    cudaGetSymbolAddress((void**)&wvh, g_Wvh);
    cudaGetSymbolAddress((void**)&wvl, g_Wvl);
    cudaGetSymbolAddress((void**)&woh, g_Woh);
    cudaGetSymbolAddress((void**)&wol, g_Wol);
    cudaGetSymbolAddress((void**)&qh,  g_Qh);
    cudaGetSymbolAddress((void**)&khb, g_Kh);
    cudaGetSymbolAddress((void**)&klb, g_Kl);
    cudaGetSymbolAddress((void**)&vhb, g_Vh);
    cudaGetSymbolAddress((void**)&vlb, g_Vl);
    cudaGetSymbolAddress((void**)&chb, g_Ch);

    cudaFuncSetAttribute(gemm_qkv,
                         cudaFuncAttributeMaxDynamicSharedMemorySize, G2_SMEM);
    cudaFuncSetAttribute(gemm_out,
                         cudaFuncAttributeMaxDynamicSharedMemorySize, G2_SMEM);
    cudaFuncSetAttribute(flash_f16,
                         cudaFuncAttributeMaxDynamicSharedMemorySize, FB_SMEM);

    split4_f16<<<4 * NW4 / 256, 256>>>(Wq, Wk, Wv, Wo,
                                       wqh, wql, wkh, wkl, wvh, wvl, woh, wol);
    cvt3_f16<<<3 * NA4 / 256, 256>>>(query, key, value, xq, xk, xv);

    gemm_qkv<<<3072, 256, G2_SMEM>>>(xq, xk, xv, wqh, wql, wkh, wkl, wvh, wvl,
                                     qh, khb, klb, vhb, vlb);

    flash_f16<<<dim3(SEQ / 64, NHEAD, BATCH), 128, FB_SMEM>>>(
        qh, khb, klb, vhb, vlb, amask, chb);

    gemm_out<<<dim3(DMODEL / 128, MROWS / 128), 256, G2_SMEM>>>(chb, woh, wol, out);
}

// round 9
// speedup vs baseline: 1.1682x; 1.0897x over previous
#include <cuda_runtime.h>
#include <cuda_fp16.h>
#include <cstdint>

// Problem constants
#define BATCH 4
#define SEQ   2048
#define DMODEL 2048
#define NHEAD 16
#define HDIM  128
#define MROWS (BATCH * SEQ)   // 8192

// ---------------------------------------------------------------------------
// Scratch (device globals; allocation in kernel_launch is forbidden)
// ---------------------------------------------------------------------------
__device__ __half g_Xq[(size_t)MROWS * DMODEL];
__device__ __half g_Xk[(size_t)MROWS * DMODEL];
__device__ __half g_Xv[(size_t)MROWS * DMODEL];
__device__ __half g_Wqh[(size_t)DMODEL * DMODEL];
__device__ __half g_Wql[(size_t)DMODEL * DMODEL];
__device__ __half g_Wkh[(size_t)DMODEL * DMODEL];
__device__ __half g_Wkl[(size_t)DMODEL * DMODEL];
__device__ __half g_Wvh[(size_t)DMODEL * DMODEL];
__device__ __half g_Wvl[(size_t)DMODEL * DMODEL];
__device__ __half g_Woh[(size_t)DMODEL * DMODEL];
__device__ __half g_Wol[(size_t)DMODEL * DMODEL];
__device__ __half g_Qh[(size_t)MROWS * DMODEL];
__device__ __half g_Kh[(size_t)MROWS * DMODEL];
__device__ __half g_Kl[(size_t)MROWS * DMODEL];
__device__ __half g_Vh[(size_t)MROWS * DMODEL];
__device__ __half g_Vl[(size_t)MROWS * DMODEL];
__device__ __half g_Ch[(size_t)MROWS * DMODEL];

// ---------------------------------------------------------------------------
// PTX helpers (sm_80-level: mma.sync / ldmatrix / cp.async)
// ---------------------------------------------------------------------------
__device__ __forceinline__ uint32_t smem_u32(const void* p) {
    uint32_t a;
    asm("{ .reg .u64 t; cvta.to.shared.u64 t, %1; cvt.u32.u64 %0, t; }"
        : "=r"(a) : "l"(p));
    return a;
}
__device__ __forceinline__ void ldsm4(uint32_t* r, uint32_t addr) {
    asm volatile("ldmatrix.sync.aligned.m8n8.x4.shared.b16 {%0,%1,%2,%3}, [%4];"
                 : "=r"(r[0]), "=r"(r[1]), "=r"(r[2]), "=r"(r[3]) : "r"(addr));
}
__device__ __forceinline__ void ldsm4t(uint32_t* r, uint32_t addr) {
    asm volatile("ldmatrix.sync.aligned.m8n8.x4.trans.shared.b16 {%0,%1,%2,%3}, [%4];"
                 : "=r"(r[0]), "=r"(r[1]), "=r"(r[2]), "=r"(r[3]) : "r"(addr));
}
__device__ __forceinline__ void mma_f16(float* d, const uint32_t* a,
                                        const uint32_t* b) {
    asm volatile(
        "mma.sync.aligned.m16n8k16.row.col.f32.f16.f16.f32 "
        "{%0,%1,%2,%3}, {%4,%5,%6,%7}, {%8,%9}, {%0,%1,%2,%3};"
        : "+f"(d[0]), "+f"(d[1]), "+f"(d[2]), "+f"(d[3])
        : "r"(a[0]), "r"(a[1]), "r"(a[2]), "r"(a[3]), "r"(b[0]), "r"(b[1]));
}
__device__ __forceinline__ void cp16(uint32_t dst, const void* src) {
    asm volatile("cp.async.cg.shared.global [%0], [%1], 16;"
                 :: "r"(dst), "l"(src) : "memory");
}
#define CP_COMMIT asm volatile("cp.async.commit_group;" ::: "memory")
#define CP_WAIT0  asm volatile("cp.async.wait_group 0;" ::: "memory")

// pack two fp32 -> half2 (first arg -> low half)
__device__ __forceinline__ uint32_t pack_h2(float lo, float hi) {
    uint32_t r;
    asm("cvt.rn.f16x2.f32 %0, %1, %2;" : "=r"(r) : "f"(hi), "f"(lo));
    return r;
}
__device__ __forceinline__ float2 h2_f2(uint32_t u) {
    __half2 h = *reinterpret_cast<__half2*>(&u);
    return __half22float2(h);
}

#define QSCALE 0.08838834764831843f   // 1/sqrt(128), folded into Q

// ---------------------------------------------------------------------------
// Fused converts
// ---------------------------------------------------------------------------
#define NA4 (MROWS * DMODEL / 4)
#define NW4 (DMODEL * DMODEL / 4)

__global__ void __launch_bounds__(256) cvt3_f16(
    const float* __restrict__ x0, const float* __restrict__ x1,
    const float* __restrict__ x2, __half* __restrict__ h0,
    __half* __restrict__ h1, __half* __restrict__ h2)
{
    int i = blockIdx.x * 256 + threadIdx.x;
    int which = i / NA4;
    int j = i - which * NA4;
    const float* x = (which == 0) ? x0 : (which == 1) ? x1 : x2;
    __half* h = (which == 0) ? h0 : (which == 1) ? h1 : h2;
    float4 v = ((const float4*)x)[j];
    ((uint2*)h)[j] = make_uint2(pack_h2(v.x, v.y), pack_h2(v.z, v.w));
}

__global__ void __launch_bounds__(256) split4_f16(
    const float* __restrict__ w0, const float* __restrict__ w1,
    const float* __restrict__ w2, const float* __restrict__ w3,
    __half* __restrict__ h0, __half* __restrict__ l0,
    __half* __restrict__ h1, __half* __restrict__ l1,
    __half* __restrict__ h2, __half* __restrict__ l2,
    __half* __restrict__ h3, __half* __restrict__ l3)
{
    int i = blockIdx.x * 256 + threadIdx.x;
    int which = i / NW4;
    int j = i - which * NW4;
    const float* x = (which == 0) ? w0 : (which == 1) ? w1
                     : (which == 2) ? w2 : w3;
    __half* hi = (which == 0) ? h0 : (which == 1) ? h1
                 : (which == 2) ? h2 : h3;
    __half* lo = (which == 0) ? l0 : (which == 1) ? l1
                 : (which == 2) ? l2 : l3;
    float4 v = ((const float4*)x)[j];
    uint32_t a0 = pack_h2(v.x, v.y);
    uint32_t a1 = pack_h2(v.z, v.w);
    float2 f0 = h2_f2(a0), f1 = h2_f2(a1);
    ((uint2*)hi)[j] = make_uint2(a0, a1);
    ((uint2*)lo)[j] = make_uint2(pack_h2(v.x - f0.x, v.y - f0.y),
                                 pack_h2(v.z - f1.x, v.w - f1.y));
}

// ---------------------------------------------------------------------------
// fp16 2-term GEMM:  C = A @ W^T ≈ Ah·Wh + Ah·Wl
// CTA 128x128, BK=64, 8 warps (2x4, warp 64x32), 2-stage cp.async double
// buffer, 2 CTAs/SM. Rows padded to 144 B (128 data + 16; conflict-free
// ldmatrix: 4-word shift per row covers all bank quads across 8 rows).
// All fragment ldsm hoisted ahead of the MMA block per k16-step.
// ---------------------------------------------------------------------------
#define G4_ROWB  144
#define G4_TILE  (128 * G4_ROWB)     // 18432
#define G4_STAGE (3 * G4_TILE)       // 55296 (A, Wh, Wl)
#define G4_SMEM  (2 * G4_STAGE)      // 110592 -> 2 CTAs/SM

__device__ __forceinline__ void g4_load(
    uint32_t smb, int stage, const __half* __restrict__ A,
    const __half* __restrict__ Wh, const __half* __restrict__ Wl,
    int m0, int n0, int k0, int tid)
{
    const __half* srcs[3] = {A + (size_t)m0 * DMODEL + k0,
                             Wh + (size_t)n0 * DMODEL + k0,
                             Wl + (size_t)n0 * DMODEL + k0};
    #pragma unroll
    for (int t = 0; t < 3; t++) {
        #pragma unroll
        for (int i = 0; i < 4; i++) {
            int v = i * 256 + tid;          // 0..1023 16B chunks
            int r = v >> 3;                 // 0..127
            int c = (v & 7) * 16;           // 0..112
            cp16(smb + stage * G4_STAGE + t * G4_TILE + r * G4_ROWB + c,
                 (const char*)srcs[t] + (size_t)r * DMODEL * 2 + c);
        }
    }
}

__device__ __forceinline__ void g4_mainloop(
    uint32_t smb, const __half* __restrict__ A, const __half* __restrict__ Wh,
    const __half* __restrict__ Wl, int m0, int n0, int tid,
    float acc[4][4][4])
{
    const int lane = tid & 31;
    const int wid  = tid >> 5;
    const int wm = wid >> 2;
    const int wn = wid & 3;
    const int a_row = wm * 64 + (lane & 15);
    const int a_cb  = ((lane >> 4) & 1) * 16;
    const int b_row = wn * 32 + (lane & 7) + ((lane >> 4) << 3);
    const int b_cb  = ((lane >> 3) & 1) * 16;

    const int nchunks = DMODEL / 64;   // 32
    g4_load(smb, 0, A, Wh, Wl, m0, n0, 0, tid);
    CP_COMMIT;

    for (int c = 0; c < nchunks; c++) {
        CP_WAIT0;            // chunk c resident
        __syncthreads();     // other stage free (compute of c-1 done)
        if (c + 1 < nchunks) {
            g4_load(smb, (c + 1) & 1, A, Wh, Wl, m0, n0, (c + 1) * 64, tid);
            CP_COMMIT;
        }

        const uint32_t st = smb + (c & 1) * G4_STAGE;
        #pragma unroll
        for (int kk = 0; kk < 4; kk++) {
            const int kb = kk * 32;
            // ---- hoist ALL fragment loads ahead of the MMA block ----
            uint32_t bh[4][2], bl[4][2];
            #pragma unroll
            for (int nt2 = 0; nt2 < 2; nt2++) {
                uint32_t r4[4];
                uint32_t baddr = st + G4_TILE +
                                 (b_row + nt2 * 16) * G4_ROWB + kb + b_cb;
                ldsm4(r4, baddr);
                bh[nt2 * 2][0] = r4[0]; bh[nt2 * 2][1] = r4[1];
                bh[nt2 * 2 + 1][0] = r4[2]; bh[nt2 * 2 + 1][1] = r4[3];
                ldsm4(r4, baddr + G4_TILE);
                bl[nt2 * 2][0] = r4[0]; bl[nt2 * 2][1] = r4[1];
                bl[nt2 * 2 + 1][0] = r4[2]; bl[nt2 * 2 + 1][1] = r4[3];
            }
            uint32_t ah[4][4];
            #pragma unroll
            for (int mt = 0; mt < 4; mt++)
                ldsm4(ah[mt], st + (a_row + mt * 16) * G4_ROWB + kb + a_cb);
            // ---- 32 MMAs, no interleaved loads ----
            #pragma unroll
            for (int mt = 0; mt < 4; mt++)
                #pragma unroll
                for (int nt = 0; nt < 4; nt++) {
                    mma_f16(acc[mt][nt], ah[mt], bh[nt]);
                    mma_f16(acc[mt][nt], ah[mt], bl[nt]);
                }
        }
    }
}

// Fused Q/K/V projection GEMM: 3072 tiles. Q gets 1/sqrt(HDIM) folded in.
__global__ void __launch_bounds__(256, 2) gemm_qkv(
    const __half* __restrict__ xq, const __half* __restrict__ xk,
    const __half* __restrict__ xv,
    const __half* __restrict__ wqh, const __half* __restrict__ wql,
    const __half* __restrict__ wkh, const __half* __restrict__ wkl,
    const __half* __restrict__ wvh, const __half* __restrict__ wvl,
    __half* __restrict__ qh, __half* __restrict__ kh, __half* __restrict__ kl,
    __half* __restrict__ vh, __half* __restrict__ vl)
{
    extern __shared__ __align__(128) char sm[];
    const uint32_t smb = smem_u32(sm);
    const int t = blockIdx.x;
    const int which = t >> 10;
    const int idx = t & 1023;
    const int m0 = (idx >> 4) * 128;
    const int n0 = (idx & 15) * 128;
    const int tid = threadIdx.x;

    const __half* A  = (which == 0) ? xq  : (which == 1) ? xk  : xv;
    const __half* Wh = (which == 0) ? wqh : (which == 1) ? wkh : wvh;
    const __half* Wl = (which == 0) ? wql : (which == 1) ? wkl : wvl;
    __half* Oh = (which == 0) ? qh : (which == 1) ? kh : vh;
    __half* Ol = (which == 1) ? kl : vl;

    float acc[4][4][4];
    #pragma unroll
    for (int i = 0; i < 4; i++)
        #pragma unroll
        for (int j = 0; j < 4; j++)
            #pragma unroll
            for (int e = 0; e < 4; e++) acc[i][j][e] = 0.0f;

    g4_mainloop(smb, A, Wh, Wl, m0, n0, tid, acc);

    const int lane = tid & 31;
    const int wid  = tid >> 5;
    const float sc = (which == 0) ? QSCALE : 1.0f;
    #pragma unroll
    for (int mt = 0; mt < 4; mt++) {
        const int row = m0 + (wid >> 2) * 64 + mt * 16 + (lane >> 2);
        #pragma unroll
        for (int nt = 0; nt < 4; nt++) {
            const int col = n0 + (wid & 3) * 32 + nt * 8 + (lane & 3) * 2;
            float a0 = acc[mt][nt][0] * sc, a1 = acc[mt][nt][1] * sc;
            float a2 = acc[mt][nt][2] * sc, a3 = acc[mt][nt][3] * sc;
            uint32_t h0 = pack_h2(a0, a1);
            uint32_t h1 = pack_h2(a2, a3);
            *(uint32_t*)&Oh[(size_t)row * DMODEL + col] = h0;
            *(uint32_t*)&Oh[(size_t)(row + 8) * DMODEL + col] = h1;
            if (which != 0) {
                float2 f0 = h2_f2(h0), f1 = h2_f2(h1);
                *(uint32_t*)&Ol[(size_t)row * DMODEL + col] =
                    pack_h2(a0 - f0.x, a1 - f0.y);
                *(uint32_t*)&Ol[(size_t)(row + 8) * DMODEL + col] =
                    pack_h2(a2 - f1.x, a3 - f1.y);
            }
        }
    }
}

// Output projection GEMM: fp32 result to d_out.
__global__ void __launch_bounds__(256, 2) gemm_out(
    const __half* __restrict__ A, const __half* __restrict__ Wh,
    const __half* __restrict__ Wl, float* __restrict__ C)
{
    extern __shared__ __align__(128) char sm[];
    const uint32_t smb = smem_u32(sm);
    const int m0 = blockIdx.y * 128;
    const int n0 = blockIdx.x * 128;
    const int tid = threadIdx.x;

    float acc[4][4][4];
    #pragma unroll
    for (int i = 0; i < 4; i++)
        #pragma unroll
        for (int j = 0; j < 4; j++)
            #pragma unroll
            for (int e = 0; e < 4; e++) acc[i][j][e] = 0.0f;

    g4_mainloop(smb, A, Wh, Wl, m0, n0, tid, acc);

    const int lane = tid & 31;
    const int wid  = tid >> 5;
    #pragma unroll
    for (int mt = 0; mt < 4; mt++) {
        const int row = m0 + (wid >> 2) * 64 + mt * 16 + (lane >> 2);
        #pragma unroll
        for (int nt = 0; nt < 4; nt++) {
            const int col = n0 + (wid & 3) * 32 + nt * 8 + (lane & 3) * 2;
            *(float2*)&C[(size_t)row * DMODEL + col] =
                make_float2(acc[mt][nt][0], acc[mt][nt][1]);
            *(float2*)&C[(size_t)(row + 8) * DMODEL + col] =
                make_float2(acc[mt][nt][2], acc[mt][nt][3]);
        }
    }
}

// ---------------------------------------------------------------------------
// Flash attention (unchanged from R8 — best config).
// BQ=64, BKV=64, 4 warps/CTA, 2 CTAs/SM; Q pre-scaled; warp-uniform
// fast paths for masking and O-rescale.
// ---------------------------------------------------------------------------
#define FB_ROWB 272
#define FB_KH   0
#define FB_KL   (64 * FB_ROWB)
#define FB_VH   (2 * 64 * FB_ROWB)
#define FB_VL   (3 * 64 * FB_ROWB)
#define FB_Q    (4 * 64 * FB_ROWB)
#define FB_MSK  (FB_Q + 64 * FB_ROWB)
#define FB_SMEM (FB_MSK + 256)

__device__ __forceinline__ void fl_loadkv64(
    uint32_t smb, const __half* __restrict__ kh,
    const __half* __restrict__ kl, const __half* __restrict__ vh,
    const __half* __restrict__ vl, const int* __restrict__ amask,
    int b, int h, int kt, int tid)
{
    const size_t krow0 = (size_t)b * SEQ + (size_t)kt * 64;
    #pragma unroll
    for (int i = 0; i < 8; i++) {
        int idx = i * 128 + tid;
        int r = idx >> 4;
        int c = (idx & 15) * 16;
        size_t go = ((krow0 + r) * DMODEL + h * HDIM) * 2 + c;
        cp16(smb + FB_KH + r * FB_ROWB + c, (const char*)kh + go);
        cp16(smb + FB_KL + r * FB_ROWB + c, (const char*)kl + go);
        cp16(smb + FB_VH + r * FB_ROWB + c, (const char*)vh + go);
        cp16(smb + FB_VL + r * FB_ROWB + c, (const char*)vl + go);
    }
    if (tid < 16)
        cp16(smb + FB_MSK + tid * 16,
             (const char*)(amask + b * SEQ + kt * 64) + tid * 16);
}

__global__ void __launch_bounds__(128) flash_f16(
    const __half* __restrict__ qh, const __half* __restrict__ kh,
    const __half* __restrict__ kl, const __half* __restrict__ vh,
    const __half* __restrict__ vl, const int* __restrict__ amask,
    __half* __restrict__ chi)
{
    extern __shared__ __align__(128) char sm[];
    const uint32_t smb = smem_u32(sm);

    const int b  = blockIdx.z;
    const int h  = blockIdx.y;
    const int qt = (int)gridDim.x - 1 - (int)blockIdx.x;
    const int tid = threadIdx.x;
    const int wid = tid >> 5;
    const int lane = tid & 31;

    const size_t qrow0 = (size_t)b * SEQ + (size_t)qt * 64;

    #pragma unroll
    for (int i = 0; i < 8; i++) {
        int idx = i * 128 + tid;
        int r = idx >> 4;
        int c = (idx & 15) * 16;
        size_t go = ((qrow0 + r) * DMODEL + h * HDIM) * 2 + c;
        cp16(smb + FB_Q + r * FB_ROWB + c, (const char*)qh + go);
    }
    fl_loadkv64(smb, kh, kl, vh, vl, amask, b, h, 0, tid);
    CP_COMMIT;

    float o[16][4];
    #pragma unroll
    for (int nt = 0; nt < 16; nt++)
        #pragma unroll
        for (int e = 0; e < 4; e++) o[nt][e] = 0.0f;
    float mA = -1e30f, mB = -1e30f, lA = 0.0f, lB = 0.0f;
    uint32_t qf[8][4];

    const int rA = lane >> 2;
    const int growA = qt * 64 + wid * 16 + rA;
    const int growB = growA + 8;
    const uint32_t qbase = smb + FB_Q + (wid * 16 + (lane & 15)) * FB_ROWB +
                           ((lane >> 4) & 1) * 16;
    const uint32_t kbase0 = smb + FB_KH +
                            ((lane & 7) + ((lane >> 4) << 3)) * FB_ROWB +
                            ((lane >> 3) & 1) * 16;
    const uint32_t vbase0 = smb + FB_VH +
                            ((lane & 7) + ((lane >> 3) & 1) * 8) * FB_ROWB +
                            (lane >> 4) * 16;

    for (int kt = 0; kt <= qt; kt++) {
        CP_WAIT0;
        __syncthreads();
        if (kt == 0) {
            #pragma unroll
            for (int kk = 0; kk < 8; kk++) ldsm4(qf[kk], qbase + kk * 32);
        }

        float s[8][4];
        #pragma unroll
        for (int nt = 0; nt < 8; nt++)
            #pragma unroll
            for (int e = 0; e < 4; e++) s[nt][e] = 0.0f;

        #pragma unroll
        for (int kk = 0; kk < 8; kk++) {
            #pragma unroll
            for (int g = 0; g < 4; g++) {
                uint32_t kf[4], lf[4];
                uint32_t baddr = kbase0 + g * 16 * FB_ROWB + kk * 32;
                ldsm4(kf, baddr);
                ldsm4(lf, baddr + FB_KL);
                mma_f16(s[2 * g], qf[kk], kf);
                mma_f16(s[2 * g], qf[kk], lf);
                mma_f16(s[2 * g + 1], qf[kk], kf + 2);
                mma_f16(s[2 * g + 1], qf[kk], lf + 2);
            }
        }

        const int* Ms = (const int*)(sm + FB_MSK);
        int mybit = (Ms[lane] != 0) & (Ms[lane + 32] != 0);
        bool allones = (__ballot_sync(0xffffffffu, mybit) == 0xffffffffu);
        float tmaxA = -1e30f, tmaxB = -1e30f;
        if (allones && (kt * 64 + 63 <= qt * 64 + wid * 16)) {
            #pragma unroll
            for (int nt = 0; nt < 8; nt++) {
                tmaxA = fmaxf(tmaxA, fmaxf(s[nt][0], s[nt][1]));
                tmaxB = fmaxf(tmaxB, fmaxf(s[nt][2], s[nt][3]));
            }
        } else {
            #pragma unroll
            for (int nt = 0; nt < 8; nt++) {
                int lc = nt * 8 + (lane & 3) * 2;
                int gc = kt * 64 + lc;
                int mk0 = Ms[lc], mk1 = Ms[lc + 1];
                float v0 = s[nt][0]; if (gc > growA || !mk0) v0 = -10000.0f;
                float v1 = s[nt][1]; if (gc + 1 > growA || !mk1) v1 = -10000.0f;
                float v2 = s[nt][2]; if (gc > growB || !mk0) v2 = -10000.0f;
                float v3 = s[nt][3]; if (gc + 1 > growB || !mk1) v3 = -10000.0f;
                s[nt][0] = v0; s[nt][1] = v1; s[nt][2] = v2; s[nt][3] = v3;
                tmaxA = fmaxf(tmaxA, fmaxf(v0, v1));
                tmaxB = fmaxf(tmaxB, fmaxf(v2, v3));
            }
        }
        tmaxA = fmaxf(tmaxA, __shfl_xor_sync(0xffffffffu, tmaxA, 1));
        tmaxA = fmaxf(tmaxA, __shfl_xor_sync(0xffffffffu, tmaxA, 2));
        tmaxB = fmaxf(tmaxB, __shfl_xor_sync(0xffffffffu, tmaxB, 1));
        tmaxB = fmaxf(tmaxB, __shfl_xor_sync(0xffffffffu, tmaxB, 2));

        float mAn = fmaxf(mA, tmaxA), mBn = fmaxf(mB, tmaxB);
        float aAl = __expf(mA - mAn), aBl = __expf(mB - mBn);

        uint32_t phi[8][2];
        float sumA = 0.0f, sumB = 0.0f;
        #pragma unroll
        for (int nt = 0; nt < 8; nt++) {
            float p0 = __expf(s[nt][0] - mAn), p1 = __expf(s[nt][1] - mAn);
            float p2 = __expf(s[nt][2] - mBn), p3 = __expf(s[nt][3] - mBn);
            sumA += p0 + p1; sumB += p2 + p3;
            phi[nt][0] = pack_h2(p0, p1);
            phi[nt][1] = pack_h2(p2, p3);
        }
        sumA += __shfl_xor_sync(0xffffffffu, sumA, 1);
        sumA += __shfl_xor_sync(0xffffffffu, sumA, 2);
        sumB += __shfl_xor_sync(0xffffffffu, sumB, 1);
        sumB += __shfl_xor_sync(0xffffffffu, sumB, 2);
        lA = lA * aAl + sumA;
        lB = lB * aBl + sumB;
        mA = mAn; mB = mBn;

        if (__ballot_sync(0xffffffffu,
                          (aAl == 1.0f) && (aBl == 1.0f)) != 0xffffffffu) {
            #pragma unroll
            for (int nt = 0; nt < 16; nt++) {
                o[nt][0] *= aAl; o[nt][1] *= aAl;
                o[nt][2] *= aBl; o[nt][3] *= aBl;
            }
        }

        #pragma unroll
        for (int t = 0; t < 4; t++) {
            uint32_t ah[4] = {phi[2 * t][0], phi[2 * t][1],
                              phi[2 * t + 1][0], phi[2 * t + 1][1]};
            #pragma unroll
            for (int g = 0; g < 8; g++) {
                uint32_t vf[4], wf[4];
                uint32_t vaddr = vbase0 + t * 16 * FB_ROWB + g * 32;
                ldsm4t(vf, vaddr);
                ldsm4t(wf, vaddr + (FB_VL - FB_VH));
                mma_f16(o[2 * g], ah, vf);
                mma_f16(o[2 * g], ah, wf);
                mma_f16(o[2 * g + 1], ah, vf + 2);
                mma_f16(o[2 * g + 1], ah, wf + 2);
            }
        }

        __syncthreads();
        if (kt < qt)
            fl_loadkv64(smb, kh, kl, vh, vl, amask, b, h, kt + 1, tid);
        CP_COMMIT;
    }

    const float invA = 1.0f / lA, invB = 1.0f / lB;
    const size_t rgA = qrow0 + wid * 16 + rA;
    const size_t rgB = rgA + 8;
    #pragma unroll
    for (int nt = 0; nt < 16; nt++) {
        int col = h * HDIM + nt * 8 + (lane & 3) * 2;
        *(uint32_t*)&chi[rgA * DMODEL + col] =
            pack_h2(o[nt][0] * invA, o[nt][1] * invA);
        *(uint32_t*)&chi[rgB * DMODEL + col] =
            pack_h2(o[nt][2] * invB, o[nt][3] * invB);
    }
}

// ---------------------------------------------------------------------------
// Launch
// ---------------------------------------------------------------------------
extern "C" void kernel_launch(void* const* d_in, const int* in_sizes, int n_in,
                              void* d_out, int out_size)
{
    const float* query = (const float*)d_in[0];
    const float* key   = (const float*)d_in[1];
    const float* value = (const float*)d_in[2];
    const int*   amask = (const int*)  d_in[3];
    const float* Wq    = (const float*)d_in[4];
    const float* Wk    = (const float*)d_in[5];
    const float* Wv    = (const float*)d_in[6];
    const float* Wo    = (const float*)d_in[7];
    float* out = (float*)d_out;

    __half *xq, *xk, *xv, *wqh, *wql, *wkh, *wkl, *wvh, *wvl, *woh, *wol;
    __half *qh, *khb, *klb, *vhb, *vlb, *chb;
    cudaGetSymbolAddress((void**)&xq,  g_Xq);
    cudaGetSymbolAddress((void**)&xk,  g_Xk);
    cudaGetSymbolAddress((void**)&xv,  g_Xv);
    cudaGetSymbolAddress((void**)&wqh, g_Wqh);
    cudaGetSymbolAddress((void**)&wql, g_Wql);
    cudaGetSymbolAddress((void**)&wkh, g_Wkh);
    cudaGetSymbolAddress((void**)&wkl, g_Wkl);
    cudaGetSymbolAddress((void**)&wvh, g_Wvh);
    cudaGetSymbolAddress((void**)&wvl, g_Wvl);
    cudaGetSymbolAddress((void**)&woh, g_Woh);
    cudaGetSymbolAddress((void**)&wol, g_Wol);
    cudaGetSymbolAddress((void**)&qh,  g_Qh);
    cudaGetSymbolAddress((void**)&khb, g_Kh);
    cudaGetSymbolAddress((void**)&klb, g_Kl);
    cudaGetSymbolAddress((void**)&vhb, g_Vh);
    cudaGetSymbolAddress((void**)&vlb, g_Vl);
    cudaGetSymbolAddress((void**)&chb, g_Ch);

    cudaFuncSetAttribute(gemm_qkv,
                         cudaFuncAttributeMaxDynamicSharedMemorySize, G4_SMEM);
    cudaFuncSetAttribute(gemm_out,
                         cudaFuncAttributeMaxDynamicSharedMemorySize, G4_SMEM);
    cudaFuncSetAttribute(flash_f16,
                         cudaFuncAttributeMaxDynamicSharedMemorySize, FB_SMEM);

    split4_f16<<<4 * NW4 / 256, 256>>>(Wq, Wk, Wv, Wo,
                                       wqh, wql, wkh, wkl, wvh, wvl, woh, wol);
    cvt3_f16<<<3 * NA4 / 256, 256>>>(query, key, value, xq, xk, xv);

    gemm_qkv<<<3072, 256, G4_SMEM>>>(xq, xk, xv, wqh, wql, wkh, wkl, wvh, wvl,
                                     qh, khb, klb, vhb, vlb);

    flash_f16<<<dim3(SEQ / 64, NHEAD, BATCH), 128, FB_SMEM>>>(
        qh, khb, klb, vhb, vlb, amask, chb);

    gemm_out<<<dim3(DMODEL / 128, MROWS / 128), 256, G4_SMEM>>>(chb, woh, wol, out);
}

// round 10
// speedup vs baseline: 2.0387x; 1.7452x over previous
#include <cuda_runtime.h>
#include <cuda_fp16.h>
#include <cstdint>

// Problem constants
#define BATCH 4
#define SEQ   2048
#define DMODEL 2048
#define NHEAD 16
#define HDIM  128
#define MROWS (BATCH * SEQ)   // 8192

// ---------------------------------------------------------------------------
// Scratch (device globals; allocation in kernel_launch is forbidden)
// ---------------------------------------------------------------------------
__device__ __half g_Xq[(size_t)MROWS * DMODEL];
__device__ __half g_Xk[(size_t)MROWS * DMODEL];
__device__ __half g_Xv[(size_t)MROWS * DMODEL];
__device__ __half g_Wq[(size_t)DMODEL * DMODEL];
__device__ __half g_Wk[(size_t)DMODEL * DMODEL];
__device__ __half g_Wv[(size_t)DMODEL * DMODEL];
__device__ __half g_Wo[(size_t)DMODEL * DMODEL];
__device__ __half g_Qh[(size_t)MROWS * DMODEL];
__device__ __half g_Kh[(size_t)MROWS * DMODEL];
__device__ __half g_Vh[(size_t)MROWS * DMODEL];
__device__ __half g_Ch[(size_t)MROWS * DMODEL];

// ---------------------------------------------------------------------------
// PTX helpers (sm_80-level: mma.sync / ldmatrix / cp.async)
// ---------------------------------------------------------------------------
__device__ __forceinline__ uint32_t smem_u32(const void* p) {
    uint32_t a;
    asm("{ .reg .u64 t; cvta.to.shared.u64 t, %1; cvt.u32.u64 %0, t; }"
        : "=r"(a) : "l"(p));
    return a;
}
__device__ __forceinline__ void ldsm4(uint32_t* r, uint32_t addr) {
    asm volatile("ldmatrix.sync.aligned.m8n8.x4.shared.b16 {%0,%1,%2,%3}, [%4];"
                 : "=r"(r[0]), "=r"(r[1]), "=r"(r[2]), "=r"(r[3]) : "r"(addr));
}
__device__ __forceinline__ void ldsm4t(uint32_t* r, uint32_t addr) {
    asm volatile("ldmatrix.sync.aligned.m8n8.x4.trans.shared.b16 {%0,%1,%2,%3}, [%4];"
                 : "=r"(r[0]), "=r"(r[1]), "=r"(r[2]), "=r"(r[3]) : "r"(addr));
}
__device__ __forceinline__ void mma_f16(float* d, const uint32_t* a,
                                        const uint32_t* b) {
    asm volatile(
        "mma.sync.aligned.m16n8k16.row.col.f32.f16.f16.f32 "
        "{%0,%1,%2,%3}, {%4,%5,%6,%7}, {%8,%9}, {%0,%1,%2,%3};"
        : "+f"(d[0]), "+f"(d[1]), "+f"(d[2]), "+f"(d[3])
        : "r"(a[0]), "r"(a[1]), "r"(a[2]), "r"(a[3]), "r"(b[0]), "r"(b[1]));
}
__device__ __forceinline__ void cp16(uint32_t dst, const void* src) {
    asm volatile("cp.async.cg.shared.global [%0], [%1], 16;"
                 :: "r"(dst), "l"(src) : "memory");
}
#define CP_COMMIT asm volatile("cp.async.commit_group;" ::: "memory")
#define CP_WAIT0  asm volatile("cp.async.wait_group 0;" ::: "memory")

// pack two fp32 -> half2 (first arg -> low half)
__device__ __forceinline__ uint32_t pack_h2(float lo, float hi) {
    uint32_t r;
    asm("cvt.rn.f16x2.f32 %0, %1, %2;" : "=r"(r) : "f"(hi), "f"(lo));
    return r;
}

#define QSCALE 0.08838834764831843f   // 1/sqrt(128), folded into Q

// ---------------------------------------------------------------------------
// Fused converts (fp32 -> fp16, hi only)
// ---------------------------------------------------------------------------
#define NA4 (MROWS * DMODEL / 4)
#define NW4 (DMODEL * DMODEL / 4)

__global__ void __launch_bounds__(256) cvt3_f16(
    const float* __restrict__ x0, const float* __restrict__ x1,
    const float* __restrict__ x2, __half* __restrict__ h0,
    __half* __restrict__ h1, __half* __restrict__ h2)
{
    int i = blockIdx.x * 256 + threadIdx.x;
    int which = i / NA4;
    int j = i - which * NA4;
    const float* x = (which == 0) ? x0 : (which == 1) ? x1 : x2;
    __half* h = (which == 0) ? h0 : (which == 1) ? h1 : h2;
    float4 v = ((const float4*)x)[j];
    ((uint2*)h)[j] = make_uint2(pack_h2(v.x, v.y), pack_h2(v.z, v.w));
}

__global__ void __launch_bounds__(256) cvt4_f16(
    const float* __restrict__ w0, const float* __restrict__ w1,
    const float* __restrict__ w2, const float* __restrict__ w3,
    __half* __restrict__ h0, __half* __restrict__ h1,
    __half* __restrict__ h2, __half* __restrict__ h3)
{
    int i = blockIdx.x * 256 + threadIdx.x;
    int which = i / NW4;
    int j = i - which * NW4;
    const float* x = (which == 0) ? w0 : (which == 1) ? w1
                     : (which == 2) ? w2 : w3;
    __half* h = (which == 0) ? h0 : (which == 1) ? h1
                : (which == 2) ? h2 : h3;
    float4 v = ((const float4*)x)[j];
    ((uint2*)h)[j] = make_uint2(pack_h2(v.x, v.y), pack_h2(v.z, v.w));
}

// ---------------------------------------------------------------------------
// fp16 single-term GEMM:  C = A @ W^T   (all operands fp16, fp32 accum)
// CTA 128x128, BK=64, 8 warps (2x4, warp 64x32), 2-stage cp.async double
// buffer, 2 CTAs/SM. Rows padded to 144 B. Fragment loads hoisted per k16.
// ---------------------------------------------------------------------------
#define G5_ROWB  144
#define G5_TILE  (128 * G5_ROWB)     // 18432
#define G5_STAGE (2 * G5_TILE)       // 36864 (A, W)
#define G5_SMEM  (2 * G5_STAGE)      // 73728 -> 2 CTAs/SM

__device__ __forceinline__ void g5_load(
    uint32_t smb, int stage, const __half* __restrict__ A,
    const __half* __restrict__ W, int m0, int n0, int k0, int tid)
{
    const __half* srcs[2] = {A + (size_t)m0 * DMODEL + k0,
                             W + (size_t)n0 * DMODEL + k0};
    #pragma unroll
    for (int t = 0; t < 2; t++) {
        #pragma unroll
        for (int i = 0; i < 4; i++) {
            int v = i * 256 + tid;          // 0..1023 16B chunks
            int r = v >> 3;                 // 0..127
            int c = (v & 7) * 16;           // 0..112
            cp16(smb + stage * G5_STAGE + t * G5_TILE + r * G5_ROWB + c,
                 (const char*)srcs[t] + (size_t)r * DMODEL * 2 + c);
        }
    }
}

__device__ __forceinline__ void g5_mainloop(
    uint32_t smb, const __half* __restrict__ A, const __half* __restrict__ W,
    int m0, int n0, int tid, float acc[4][4][4])
{
    const int lane = tid & 31;
    const int wid  = tid >> 5;
    const int wm = wid >> 2;
    const int wn = wid & 3;
    const int a_row = wm * 64 + (lane & 15);
    const int a_cb  = ((lane >> 4) & 1) * 16;
    const int b_row = wn * 32 + (lane & 7) + ((lane >> 4) << 3);
    const int b_cb  = ((lane >> 3) & 1) * 16;

    const int nchunks = DMODEL / 64;   // 32
    g5_load(smb, 0, A, W, m0, n0, 0, tid);
    CP_COMMIT;

    for (int c = 0; c < nchunks; c++) {
        CP_WAIT0;
        __syncthreads();
        if (c + 1 < nchunks) {
            g5_load(smb, (c + 1) & 1, A, W, m0, n0, (c + 1) * 64, tid);
            CP_COMMIT;
        }

        const uint32_t st = smb + (c & 1) * G5_STAGE;
        #pragma unroll
        for (int kk = 0; kk < 4; kk++) {
            const int kb = kk * 32;
            uint32_t bh[4][2];
            #pragma unroll
            for (int nt2 = 0; nt2 < 2; nt2++) {
                uint32_t r4[4];
                ldsm4(r4, st + G5_TILE +
                          (b_row + nt2 * 16) * G5_ROWB + kb + b_cb);
                bh[nt2 * 2][0] = r4[0]; bh[nt2 * 2][1] = r4[1];
                bh[nt2 * 2 + 1][0] = r4[2]; bh[nt2 * 2 + 1][1] = r4[3];
            }
            uint32_t ah[4][4];
            #pragma unroll
            for (int mt = 0; mt < 4; mt++)
                ldsm4(ah[mt], st + (a_row + mt * 16) * G5_ROWB + kb + a_cb);
            #pragma unroll
            for (int mt = 0; mt < 4; mt++)
                #pragma unroll
                for (int nt = 0; nt < 4; nt++)
                    mma_f16(acc[mt][nt], ah[mt], bh[nt]);
        }
    }
}

// Fused Q/K/V projection GEMM: 3072 tiles. Q gets 1/sqrt(HDIM) folded in.
__global__ void __launch_bounds__(256, 2) gemm_qkv(
    const __half* __restrict__ xq, const __half* __restrict__ xk,
    const __half* __restrict__ xv,
    const __half* __restrict__ wq, const __half* __restrict__ wk,
    const __half* __restrict__ wv,
    __half* __restrict__ qh, __half* __restrict__ kh, __half* __restrict__ vh)
{
    extern __shared__ __align__(128) char sm[];
    const uint32_t smb = smem_u32(sm);
    const int t = blockIdx.x;
    const int which = t >> 10;
    const int idx = t & 1023;
    const int m0 = (idx >> 4) * 128;
    const int n0 = (idx & 15) * 128;
    const int tid = threadIdx.x;

    const __half* A = (which == 0) ? xq : (which == 1) ? xk : xv;
    const __half* W = (which == 0) ? wq : (which == 1) ? wk : wv;
    __half* Oh = (which == 0) ? qh : (which == 1) ? kh : vh;

    float acc[4][4][4];
    #pragma unroll
    for (int i = 0; i < 4; i++)
        #pragma unroll
        for (int j = 0; j < 4; j++)
            #pragma unroll
            for (int e = 0; e < 4; e++) acc[i][j][e] = 0.0f;

    g5_mainloop(smb, A, W, m0, n0, tid, acc);

    const int lane = tid & 31;
    const int wid  = tid >> 5;
    const float sc = (which == 0) ? QSCALE : 1.0f;
    #pragma unroll
    for (int mt = 0; mt < 4; mt++) {
        const int row = m0 + (wid >> 2) * 64 + mt * 16 + (lane >> 2);
        #pragma unroll
        for (int nt = 0; nt < 4; nt++) {
            const int col = n0 + (wid & 3) * 32 + nt * 8 + (lane & 3) * 2;
            *(uint32_t*)&Oh[(size_t)row * DMODEL + col] =
                pack_h2(acc[mt][nt][0] * sc, acc[mt][nt][1] * sc);
            *(uint32_t*)&Oh[(size_t)(row + 8) * DMODEL + col] =
                pack_h2(acc[mt][nt][2] * sc, acc[mt][nt][3] * sc);
        }
    }
}

// Output projection GEMM: fp32 result to d_out.
__global__ void __launch_bounds__(256, 2) gemm_out(
    const __half* __restrict__ A, const __half* __restrict__ W,
    float* __restrict__ C)
{
    extern __shared__ __align__(128) char sm[];
    const uint32_t smb = smem_u32(sm);
    const int m0 = blockIdx.y * 128;
    const int n0 = blockIdx.x * 128;
    const int tid = threadIdx.x;

    float acc[4][4][4];
    #pragma unroll
    for (int i = 0; i < 4; i++)
        #pragma unroll
        for (int j = 0; j < 4; j++)
            #pragma unroll
            for (int e = 0; e < 4; e++) acc[i][j][e] = 0.0f;

    g5_mainloop(smb, A, W, m0, n0, tid, acc);

    const int lane = tid & 31;
    const int wid  = tid >> 5;
    #pragma unroll
    for (int mt = 0; mt < 4; mt++) {
        const int row = m0 + (wid >> 2) * 64 + mt * 16 + (lane >> 2);
        #pragma unroll
        for (int nt = 0; nt < 4; nt++) {
            const int col = n0 + (wid & 3) * 32 + nt * 8 + (lane & 3) * 2;
            *(float2*)&C[(size_t)row * DMODEL + col] =
                make_float2(acc[mt][nt][0], acc[mt][nt][1]);
            *(float2*)&C[(size_t)(row + 8) * DMODEL + col] =
                make_float2(acc[mt][nt][2], acc[mt][nt][3]);
        }
    }
}

// ---------------------------------------------------------------------------
// Flash attention, pure fp16 HMMA. BQ=64, BKV=64, 4 warps/CTA, 3 CTAs/SM.
// Single-term QK and PV. Q pre-scaled; warp-uniform fast paths.
// ---------------------------------------------------------------------------
#define FB_ROWB 272
#define FB_K    0
#define FB_V    (64 * FB_ROWB)              // 17408
#define FB_Q    (2 * 64 * FB_ROWB)          // 34816
#define FB_MSK  (FB_Q + 64 * FB_ROWB)       // 52224
#define FB_SMEM (FB_MSK + 256)              // 52480 -> 3+ CTAs/SM by smem

__device__ __forceinline__ void fl_loadkv64(
    uint32_t smb, const __half* __restrict__ kh, const __half* __restrict__ vh,
    const int* __restrict__ amask, int b, int h, int kt, int tid)
{
    const size_t krow0 = (size_t)b * SEQ + (size_t)kt * 64;
    #pragma unroll
    for (int i = 0; i < 8; i++) {
        int idx = i * 128 + tid;
        int r = idx >> 4;
        int c = (idx & 15) * 16;
        size_t go = ((krow0 + r) * DMODEL + h * HDIM) * 2 + c;
        cp16(smb + FB_K + r * FB_ROWB + c, (const char*)kh + go);
        cp16(smb + FB_V + r * FB_ROWB + c, (const char*)vh + go);
    }
    if (tid < 16)
        cp16(smb + FB_MSK + tid * 16,
             (const char*)(amask + b * SEQ + kt * 64) + tid * 16);
}

__global__ void __launch_bounds__(128, 3) flash_f16(
    const __half* __restrict__ qh, const __half* __restrict__ kh,
    const __half* __restrict__ vh, const int* __restrict__ amask,
    __half* __restrict__ chi)
{
    extern __shared__ __align__(128) char sm[];
    const uint32_t smb = smem_u32(sm);

    const int b  = blockIdx.z;
    const int h  = blockIdx.y;
    const int qt = (int)gridDim.x - 1 - (int)blockIdx.x;   // heavy tiles first
    const int tid = threadIdx.x;
    const int wid = tid >> 5;
    const int lane = tid & 31;

    const size_t qrow0 = (size_t)b * SEQ + (size_t)qt * 64;

    // Q tile (pre-scaled) -> smem
    #pragma unroll
    for (int i = 0; i < 8; i++) {
        int idx = i * 128 + tid;
        int r = idx >> 4;
        int c = (idx & 15) * 16;
        size_t go = ((qrow0 + r) * DMODEL + h * HDIM) * 2 + c;
        cp16(smb + FB_Q + r * FB_ROWB + c, (const char*)qh + go);
    }
    fl_loadkv64(smb, kh, vh, amask, b, h, 0, tid);
    CP_COMMIT;

    float o[16][4];
    #pragma unroll
    for (int nt = 0; nt < 16; nt++)
        #pragma unroll
        for (int e = 0; e < 4; e++) o[nt][e] = 0.0f;
    float mA = -1e30f, mB = -1e30f, lA = 0.0f, lB = 0.0f;
    uint32_t qf[8][4];

    const int rA = lane >> 2;
    const int growA = qt * 64 + wid * 16 + rA;
    const int growB = growA + 8;
    const uint32_t qbase = smb + FB_Q + (wid * 16 + (lane & 15)) * FB_ROWB +
                           ((lane >> 4) & 1) * 16;
    const uint32_t kbase0 = smb + FB_K +
                            ((lane & 7) + ((lane >> 4) << 3)) * FB_ROWB +
                            ((lane >> 3) & 1) * 16;
    const uint32_t vbase0 = smb + FB_V +
                            ((lane & 7) + ((lane >> 3) & 1) * 8) * FB_ROWB +
                            (lane >> 4) * 16;

    for (int kt = 0; kt <= qt; kt++) {
        CP_WAIT0;
        __syncthreads();
        if (kt == 0) {
            #pragma unroll
            for (int kk = 0; kk < 8; kk++) ldsm4(qf[kk], qbase + kk * 32);
        }

        // ---- S = Qs K^T ----
        float s[8][4];
        #pragma unroll
        for (int nt = 0; nt < 8; nt++)
            #pragma unroll
            for (int e = 0; e < 4; e++) s[nt][e] = 0.0f;

        #pragma unroll
        for (int kk = 0; kk < 8; kk++) {
            #pragma unroll
            for (int g = 0; g < 4; g++) {
                uint32_t kf[4];
                ldsm4(kf, kbase0 + g * 16 * FB_ROWB + kk * 32);
                mma_f16(s[2 * g], qf[kk], kf);
                mma_f16(s[2 * g + 1], qf[kk], kf + 2);
            }
        }

        // ---- mask (warp-uniform fast path) + row max ----
        const int* Ms = (const int*)(sm + FB_MSK);
        int mybit = (Ms[lane] != 0) & (Ms[lane + 32] != 0);
        bool allones = (__ballot_sync(0xffffffffu, mybit) == 0xffffffffu);
        float tmaxA = -1e30f, tmaxB = -1e30f;
        if (allones && (kt * 64 + 63 <= qt * 64 + wid * 16)) {
            #pragma unroll
            for (int nt = 0; nt < 8; nt++) {
                tmaxA = fmaxf(tmaxA, fmaxf(s[nt][0], s[nt][1]));
                tmaxB = fmaxf(tmaxB, fmaxf(s[nt][2], s[nt][3]));
            }
        } else {
            #pragma unroll
            for (int nt = 0; nt < 8; nt++) {
                int lc = nt * 8 + (lane & 3) * 2;
                int gc = kt * 64 + lc;
                int mk0 = Ms[lc], mk1 = Ms[lc + 1];
                float v0 = s[nt][0]; if (gc > growA || !mk0) v0 = -10000.0f;
                float v1 = s[nt][1]; if (gc + 1 > growA || !mk1) v1 = -10000.0f;
                float v2 = s[nt][2]; if (gc > growB || !mk0) v2 = -10000.0f;
                float v3 = s[nt][3]; if (gc + 1 > growB || !mk1) v3 = -10000.0f;
                s[nt][0] = v0; s[nt][1] = v1; s[nt][2] = v2; s[nt][3] = v3;
                tmaxA = fmaxf(tmaxA, fmaxf(v0, v1));
                tmaxB = fmaxf(tmaxB, fmaxf(v2, v3));
            }
        }
        tmaxA = fmaxf(tmaxA, __shfl_xor_sync(0xffffffffu, tmaxA, 1));
        tmaxA = fmaxf(tmaxA, __shfl_xor_sync(0xffffffffu, tmaxA, 2));
        tmaxB = fmaxf(tmaxB, __shfl_xor_sync(0xffffffffu, tmaxB, 1));
        tmaxB = fmaxf(tmaxB, __shfl_xor_sync(0xffffffffu, tmaxB, 2));

        float mAn = fmaxf(mA, tmaxA), mBn = fmaxf(mB, tmaxB);
        float aAl = __expf(mA - mAn), aBl = __expf(mB - mBn);

        // ---- P = exp(S - m) -> fp16 fragments ----
        uint32_t phi[8][2];
        float sumA = 0.0f, sumB = 0.0f;
        #pragma unroll
        for (int nt = 0; nt < 8; nt++) {
            float p0 = __expf(s[nt][0] - mAn), p1 = __expf(s[nt][1] - mAn);
            float p2 = __expf(s[nt][2] - mBn), p3 = __expf(s[nt][3] - mBn);
            sumA += p0 + p1; sumB += p2 + p3;
            phi[nt][0] = pack_h2(p0, p1);
            phi[nt][1] = pack_h2(p2, p3);
        }
        sumA += __shfl_xor_sync(0xffffffffu, sumA, 1);
        sumA += __shfl_xor_sync(0xffffffffu, sumA, 2);
        sumB += __shfl_xor_sync(0xffffffffu, sumB, 1);
        sumB += __shfl_xor_sync(0xffffffffu, sumB, 2);
        lA = lA * aAl + sumA;
        lB = lB * aBl + sumB;
        mA = mAn; mB = mBn;

        // ---- O rescale (skip when no row max moved in this warp) ----
        if (__ballot_sync(0xffffffffu,
                          (aAl == 1.0f) && (aBl == 1.0f)) != 0xffffffffu) {
            #pragma unroll
            for (int nt = 0; nt < 16; nt++) {
                o[nt][0] *= aAl; o[nt][1] *= aAl;
                o[nt][2] *= aBl; o[nt][3] *= aBl;
            }
        }

        // ---- O += P V ----
        #pragma unroll
        for (int t = 0; t < 4; t++) {
            uint32_t ah[4] = {phi[2 * t][0], phi[2 * t][1],
                              phi[2 * t + 1][0], phi[2 * t + 1][1]};
            #pragma unroll
            for (int g = 0; g < 8; g++) {
                uint32_t vf[4];
                ldsm4t(vf, vbase0 + t * 16 * FB_ROWB + g * 32);
                mma_f16(o[2 * g], ah, vf);
                mma_f16(o[2 * g + 1], ah, vf + 2);
            }
        }

        __syncthreads();   // all warps done reading the KV buffer
        if (kt < qt)
            fl_loadkv64(smb, kh, vh, amask, b, h, kt + 1, tid);
        CP_COMMIT;
    }

    // ---- normalize + store context (fp16) ----
    const float invA = 1.0f / lA, invB = 1.0f / lB;
    const size_t rgA = qrow0 + wid * 16 + rA;
    const size_t rgB = rgA + 8;
    #pragma unroll
    for (int nt = 0; nt < 16; nt++) {
        int col = h * HDIM + nt * 8 + (lane & 3) * 2;
        *(uint32_t*)&chi[rgA * DMODEL + col] =
            pack_h2(o[nt][0] * invA, o[nt][1] * invA);
        *(uint32_t*)&chi[rgB * DMODEL + col] =
            pack_h2(o[nt][2] * invB, o[nt][3] * invB);
    }
}

// ---------------------------------------------------------------------------
// Launch
// ---------------------------------------------------------------------------
extern "C" void kernel_launch(void* const* d_in, const int* in_sizes, int n_in,
                              void* d_out, int out_size)
{
    const float* query = (const float*)d_in[0];
    const float* key   = (const float*)d_in[1];
    const float* value = (const float*)d_in[2];
    const int*   amask = (const int*)  d_in[3];
    const float* Wq    = (const float*)d_in[4];
    const float* Wk    = (const float*)d_in[5];
    const float* Wv    = (const float*)d_in[6];
    const float* Wo    = (const float*)d_in[7];
    float* out = (float*)d_out;

    __half *xq, *xk, *xv, *wq, *wk, *wv, *wo, *qh, *kh, *vh, *ch;
    cudaGetSymbolAddress((void**)&xq, g_Xq);
    cudaGetSymbolAddress((void**)&xk, g_Xk);
    cudaGetSymbolAddress((void**)&xv, g_Xv);
    cudaGetSymbolAddress((void**)&wq, g_Wq);
    cudaGetSymbolAddress((void**)&wk, g_Wk);
    cudaGetSymbolAddress((void**)&wv, g_Wv);
    cudaGetSymbolAddress((void**)&wo, g_Wo);
    cudaGetSymbolAddress((void**)&qh, g_Qh);
    cudaGetSymbolAddress((void**)&kh, g_Kh);
    cudaGetSymbolAddress((void**)&vh, g_Vh);
    cudaGetSymbolAddress((void**)&ch, g_Ch);

    cudaFuncSetAttribute(gemm_qkv,
                         cudaFuncAttributeMaxDynamicSharedMemorySize, G5_SMEM);
    cudaFuncSetAttribute(gemm_out,
                         cudaFuncAttributeMaxDynamicSharedMemorySize, G5_SMEM);
    cudaFuncSetAttribute(flash_f16,
                         cudaFuncAttributeMaxDynamicSharedMemorySize, FB_SMEM);

    cvt4_f16<<<4 * NW4 / 256, 256>>>(Wq, Wk, Wv, Wo, wq, wk, wv, wo);
    cvt3_f16<<<3 * NA4 / 256, 256>>>(query, key, value, xq, xk, xv);

    gemm_qkv<<<3072, 256, G5_SMEM>>>(xq, xk, xv, wq, wk, wv, qh, kh, vh);

    flash_f16<<<dim3(SEQ / 64, NHEAD, BATCH), 128, FB_SMEM>>>(
        qh, kh, vh, amask, ch);

    gemm_out<<<dim3(DMODEL / 128, MROWS / 128), 256, G5_SMEM>>>(ch, wo, out);
}